// round 14
// baseline (speedup 1.0000x reference)
#include <cuda_runtime.h>
#include <cuda_bf16.h>
#include <math.h>
#include <stdint.h>

// Problem constants
#define BB 4
#define SS 4096
#define EE 1024
#define HH 128
#define CC 128
#define NCHUNK (SS/CC)
#define GAMMA 0.96875f
#define LG2G  (-0.04580368938794f)
#define LOG2_10000 13.287712379549449

// -------- scratch --------
__device__ float g_Q[BB*SS*HH];
__device__ float g_K[BB*SS*HH];
__device__ float g_V[BB*SS*HH];
__device__ float g_A[BB*NCHUNK*HH*HH];                 // T_c = A_c^T  [h2][h1], fp32
__device__ __nv_bfloat16 g_Sth[BB*NCHUNK*HH*HH];       // state hi, [h2][h1]
__device__ __nv_bfloat16 g_Stl[BB*NCHUNK*HH*HH];       // state lo
// xpos tables: [d][s1] / [d][s0]; (sin, cos, scale, 1/scale)
__device__ float4 g_tabA[64][64];
__device__ float4 g_tabB[64][64];

// ==================== table build ====================
__global__ void build_tab_kernel() {
    int idx = blockIdx.x * 256 + threadIdx.x;      // 0..8191
    int which = idx >> 12;
    int d  = (idx >> 6) & 63;
    int sX = idx & 63;
    double invf = exp2(-(double)d * (LOG2_10000 / 64.0));
    float sv = (2.0f * (float)d + 51.2f) * (1.0f / 179.2f);
    float ang, pw;
    if (which == 0) { ang = (float)((double)(sX * 64) * invf); pw = powf(sv, (float)sX * 0.125f); }
    else            { ang = (float)((double)sX * invf);        pw = powf(sv, (float)sX * (1.0f/512.0f)); }
    float sn, cs; sincosf(ang, &sn, &cs);
    float4 r = make_float4(sn, cs, pw, 1.0f / pw);
    if (which == 0) g_tabA[d][sX] = r; else g_tabB[d][sX] = r;
}

// ==================== helpers ====================
__device__ __forceinline__ void mma_bf16(float* d, const uint32_t* a, uint32_t b0, uint32_t b1) {
    asm volatile("mma.sync.aligned.m16n8k16.row.col.f32.bf16.bf16.f32 "
        "{%0,%1,%2,%3}, {%4,%5,%6,%7}, {%8,%9}, {%0,%1,%2,%3};"
        : "+f"(d[0]), "+f"(d[1]), "+f"(d[2]), "+f"(d[3])
        : "r"(a[0]), "r"(a[1]), "r"(a[2]), "r"(a[3]), "r"(b0), "r"(b1));
}

__device__ __forceinline__ void mma_f16(float* d, const uint32_t* a, uint32_t b0, uint32_t b1) {
    asm volatile("mma.sync.aligned.m16n8k16.row.col.f32.f16.f16.f32 "
        "{%0,%1,%2,%3}, {%4,%5,%6,%7}, {%8,%9}, {%0,%1,%2,%3};"
        : "+f"(d[0]), "+f"(d[1]), "+f"(d[2]), "+f"(d[3])
        : "r"(a[0]), "r"(a[1]), "r"(a[2]), "r"(a[3]), "r"(b0), "r"(b1));
}

__device__ __forceinline__ uint32_t pack_bf16x2(float x, float y) {
    uint32_t r;
    asm("cvt.rn.bf16x2.f32 %0, %1, %2;" : "=r"(r) : "f"(y), "f"(x));
    return r;
}

__device__ __forceinline__ uint32_t pack_f16x2(float x, float y) {
    uint32_t r;
    asm("cvt.rn.f16x2.f32 %0, %1, %2;" : "=r"(r) : "f"(y), "f"(x));
    return r;
}

__device__ __forceinline__ void split4(float4 v, uint2& hi, uint2& lo) {
    uint32_t hi01 = pack_bf16x2(v.x, v.y);
    uint32_t hi23 = pack_bf16x2(v.z, v.w);
    float l0 = v.x - __uint_as_float(hi01 << 16);
    float l1 = v.y - __uint_as_float(hi01 & 0xFFFF0000u);
    float l2 = v.z - __uint_as_float(hi23 << 16);
    float l3 = v.w - __uint_as_float(hi23 & 0xFFFF0000u);
    hi = make_uint2(hi01, hi23);
    lo = make_uint2(pack_bf16x2(l0, l1), pack_bf16x2(l2, l3));
}

__device__ __forceinline__ void split_store(char* hiP, char* loP, uint32_t off, float4 v) {
    uint2 hi, lo;
    split4(v, hi, lo);
    *(uint2*)(hiP + off) = hi;
    *(uint2*)(loP + off) = lo;
}

__device__ __forceinline__ void split1(float x, __nv_bfloat16& h, __nv_bfloat16& l) {
    h = __float2bfloat16(x);
    l = __float2bfloat16(x - __bfloat162float(h));
}

// ==================== projection GEMM: single-product fp16, 1 CTA/SM ====================
#define ROWB 72
#define TILEB (128*ROWB)
#define PROJ_SMEM (4*TILEB)            // layout: 2 stages x 2 tiles
#define PROJ_SMEM_ALLOC (120*1024)     // padded to force 1 CTA/SM (>113.5 KB)

__device__ __forceinline__ uint32_t lds32(const char* base, int row, int word) {
    return *(const uint32_t*)(base + row * ROWB + word * 4);
}

__global__ __launch_bounds__(256, 1)
void proj_mma_kernel(const float* __restrict__ q, const float* __restrict__ k,
                     const float* __restrict__ v,
                     const float* __restrict__ Wq, const float* __restrict__ bq,
                     const float* __restrict__ Wk, const float* __restrict__ bk,
                     const float* __restrict__ Wv, const float* __restrict__ bv)
{
    extern __shared__ char sm[];
    __shared__ float s_bias[HH];

    const int z = blockIdx.y;
    const float* X   = (z == 0) ? q  : (z == 1) ? k  : v;
    const float* W   = (z == 0) ? Wq : (z == 1) ? Wk : Wv;
    const float* bia = (z == 0) ? bq : (z == 1) ? bk : bv;
    float* OUT       = (z == 0) ? g_Q : (z == 1) ? g_K : g_V;

    const int tid  = threadIdx.x;
    const int wid  = tid >> 5;
    const int lane = tid & 31;
    const int warpM = wid & 3;
    const int warpN = wid >> 2;
    const int m0 = blockIdx.x * 128;

    if (tid < HH) s_bias[tid] = bia[tid];

    #define TILE_PTR(s, wch) (sm + ((s) * 2 + (wch)) * TILEB)

    float acc[2][8][4];
    #pragma unroll
    for (int r = 0; r < 2; r++)
        #pragma unroll
        for (int j = 0; j < 8; j++)
            #pragma unroll
            for (int c = 0; c < 4; c++) acc[r][j][c] = 0.f;

    const int ldRow = tid >> 3;
    const int ldC4  = tid & 7;
    float4 aV[4], wV[4];

    #pragma unroll
    for (int it = 0; it < 4; it++) {
        int row = ldRow + it * 32;
        aV[it] = *(const float4*)&X[(size_t)(m0 + row) * EE + ldC4 * 4];
        wV[it] = *(const float4*)&W[(size_t)row * EE + ldC4 * 4];
    }
    {
        uint32_t off = (uint32_t)ldRow * ROWB + ldC4 * 8;
        #pragma unroll
        for (int it = 0; it < 4; it++) {
            uint32_t o = off + it * 32 * ROWB;
            *(uint2*)(TILE_PTR(0,0) + o) = make_uint2(pack_f16x2(aV[it].x, aV[it].y),
                                                      pack_f16x2(aV[it].z, aV[it].w));
            *(uint2*)(TILE_PTR(0,1) + o) = make_uint2(pack_f16x2(wV[it].x, wV[it].y),
                                                      pack_f16x2(wV[it].z, wV[it].w));
        }
    }
    __syncthreads();

    const int rA = lane >> 2;
    const int wBase = lane & 3;

    for (int i = 0; i < 32; i++) {
        const int s = i & 1;
        if (i < 31) {
            const int k0 = (i + 1) * 32;
            #pragma unroll
            for (int it = 0; it < 4; it++) {
                int row = ldRow + it * 32;
                aV[it] = *(const float4*)&X[(size_t)(m0 + row) * EE + k0 + ldC4 * 4];
                wV[it] = *(const float4*)&W[(size_t)row * EE + k0 + ldC4 * 4];
            }
        }

        const char* At = TILE_PTR(s, 0);
        const char* Wt = TILE_PTR(s, 1);

        #pragma unroll
        for (int k16 = 0; k16 < 2; k16++) {
            const int w = k16 * 8 + wBase;
            uint32_t af[2][4];
            #pragma unroll
            for (int r = 0; r < 2; r++) {
                int row = warpM * 32 + r * 16 + rA;
                af[r][0] = lds32(At, row,     w);
                af[r][1] = lds32(At, row + 8, w);
                af[r][2] = lds32(At, row,     w + 4);
                af[r][3] = lds32(At, row + 8, w + 4);
            }
            #pragma unroll
            for (int j = 0; j < 8; j++) {
                int n = warpN * 64 + j * 8 + rA;
                uint32_t b0 = lds32(Wt, n, w);
                uint32_t b1 = lds32(Wt, n, w + 4);
                #pragma unroll
                for (int r = 0; r < 2; r++)
                    mma_f16(acc[r][j], af[r], b0, b1);
            }
        }

        if (i < 31) {
            uint32_t off = (uint32_t)ldRow * ROWB + ldC4 * 8;
            const int ns = (i + 1) & 1;
            #pragma unroll
            for (int it = 0; it < 4; it++) {
                uint32_t o = off + it * 32 * ROWB;
                *(uint2*)(TILE_PTR(ns,0) + o) = make_uint2(pack_f16x2(aV[it].x, aV[it].y),
                                                           pack_f16x2(aV[it].z, aV[it].w));
                *(uint2*)(TILE_PTR(ns,1) + o) = make_uint2(pack_f16x2(wV[it].x, wV[it].y),
                                                           pack_f16x2(wV[it].z, wV[it].w));
            }
            __syncthreads();
        }
    }

    #pragma unroll
    for (int r = 0; r < 2; r++) {
        #pragma unroll
        for (int half = 0; half < 2; half++) {
            const int m = m0 + warpM * 32 + r * 16 + rA + half * 8;
            const int sIdx = m & (SS - 1);
            const int s1 = sIdx >> 6;
            const int s0 = sIdx & 63;
            float* orow = OUT + (size_t)m * HH;
            #pragma unroll
            for (int j = 0; j < 8; j++) {
                const int h = warpN * 64 + j * 8 + wBase * 2;
                float x0 = acc[r][j][half * 2 + 0] + s_bias[h];
                float x1 = acc[r][j][half * 2 + 1] + s_bias[h + 1];
                if (z == 2) {
                    *(float2*)&orow[h] = make_float2(x0, x1);
                } else {
                    const int d = h >> 1;
                    float4 A4 = g_tabA[d][s1];
                    float4 B4 = g_tabB[d][s0];
                    float sn = A4.x * B4.y + A4.y * B4.x;
                    float cs = A4.y * B4.y - A4.x * B4.x;
                    float sc = (z == 0) ? A4.z * B4.z : A4.w * B4.w;
                    sn *= sc; cs *= sc;
                    *(float2*)&orow[h] = make_float2(x0 * cs - x1 * sn, x1 * cs + x0 * sn);
                }
            }
        }
    }
    #undef TILE_PTR
}

// ==================== shared tile constants for retention kernels ====================
#define RS 272
#define TB (128*RS)
#define CHUNK_SMEM (4*TB + 512)
#define INTRA_SMEM (6*TB + 1024)

template<int NT>
__device__ __forceinline__ void load_split_rows_t(const float* src, char* bh, char* bl,
                                                  int tid, const float* rowScale) {
    #pragma unroll
    for (int it = 0; it < 4096 / NT; it++) {
        int idx = it * NT + tid;
        int row = idx >> 5;
        int c4  = idx & 31;
        float4 v = *(const float4*)&src[(size_t)row * HH + c4 * 4];
        if (rowScale) {
            float s = rowScale[row];
            v.x *= s; v.y *= s; v.z *= s; v.w *= s;
        }
        split_store(bh, bl, (uint32_t)row * RS + c4 * 8, v);
    }
}

// transpose load+split with bank-conflict-reduced pair stores (R12 winner).
template<int NT>
__device__ __forceinline__ void load_split_trans_t(const float* src, char* bh, char* bl,
                                                   int tid, const float* jScale) {
    #pragma unroll
    for (int it = 0; it < 2048 / NT; it++) {
        int idx = it * NT + tid;
        int h8    = idx & 7;
        int jp2   = (idx >> 3) & 3;
        int houter = (idx >> 5) & 3;
        int jouter = idx >> 7;          // 0..15
        int h4 = houter * 8 + h8;       // 0..31
        int jp = jouter * 4 + jp2;      // 0..63
        int j0 = jp * 2;

        float4 va = *(const float4*)&src[(size_t)j0 * HH + h4 * 4];
        float4 vb = *(const float4*)&src[(size_t)(j0 + 1) * HH + h4 * 4];
        if (jScale) {
            float sa = jScale[j0], sb = jScale[j0 + 1];
            va.x *= sa; va.y *= sa; va.z *= sa; va.w *= sa;
            vb.x *= sb; vb.y *= sb; vb.z *= sb; vb.w *= sb;
        }
        float a[4] = {va.x, va.y, va.z, va.w};
        float b[4] = {vb.x, vb.y, vb.z, vb.w};
        #pragma unroll
        for (int e = 0; e < 4; e++) {
            uint32_t hi = pack_bf16x2(a[e], b[e]);
            float la = a[e] - __uint_as_float(hi << 16);
            float lb = b[e] - __uint_as_float(hi & 0xFFFF0000u);
            uint32_t lo = pack_bf16x2(la, lb);
            uint32_t off = (uint32_t)(h4 * 4 + e) * RS + j0 * 2;
            *(uint32_t*)(bh + off) = hi;
            *(uint32_t*)(bl + off) = lo;
        }
    }
}

// ==================== chunk summary ====================
__global__ __launch_bounds__(512, 1)
void chunk_t_kernel()
{
    extern __shared__ char sm[];
    char* Vth = sm;
    char* Vtl = sm + TB;
    char* Kth = sm + 2*TB;
    char* Ktl = sm + 3*TB;
    float* gpos = (float*)(sm + 4*TB);

    const int bc = blockIdx.x;
    const int b = bc >> 5;
    const int c = bc & 31;
    const float* Kp = g_K + (size_t)(b * SS + c * CC) * HH;
    const float* Vp = g_V + (size_t)(b * SS + c * CC) * HH;
    float* Tp = g_A + (size_t)bc * HH * HH;

    const int tid = threadIdx.x;
    const int wid = tid >> 5;
    const int lane = tid & 31;
    const int rA = lane >> 2;
    const int wq = lane & 3;

    __shared__ float kScale[128];
    if (tid < 128) {
        gpos[tid] = exp2f((float)tid * LG2G);
        kScale[tid] = exp2f((float)(127 - tid) * LG2G);
    }
    __syncthreads();

    load_split_trans_t<512>(Vp, Vth, Vtl, tid, nullptr);
    load_split_trans_t<512>(Kp, Kth, Ktl, tid, kScale);
    __syncthreads();

    const int m0 = (wid >> 1) * 16;
    const int noff = (wid & 1) * 8;
    float acc[8][4];
    #pragma unroll
    for (int n8 = 0; n8 < 8; n8++)
        #pragma unroll
        for (int cc = 0; cc < 4; cc++) acc[n8][cc] = 0.f;

    #pragma unroll
    for (int kk = 0; kk < 8; kk++) {
        const uint32_t kb = kk * 32 + wq * 4;
        uint32_t ah[4], al[4];
        ah[0] = *(uint32_t*)(Vth + (m0 + rA) * RS + kb);
        ah[1] = *(uint32_t*)(Vth + (m0 + rA + 8) * RS + kb);
        ah[2] = *(uint32_t*)(Vth + (m0 + rA) * RS + kb + 16);
        ah[3] = *(uint32_t*)(Vth + (m0 + rA + 8) * RS + kb + 16);
        al[0] = *(uint32_t*)(Vtl + (m0 + rA) * RS + kb);
        al[1] = *(uint32_t*)(Vtl + (m0 + rA + 8) * RS + kb);
        al[2] = *(uint32_t*)(Vtl + (m0 + rA) * RS + kb + 16);
        al[3] = *(uint32_t*)(Vtl + (m0 + rA + 8) * RS + kb + 16);
        #pragma unroll
        for (int n8 = 0; n8 < 8; n8++) {
            int nrow = (noff + n8) * 8 + rA;
            uint32_t bh0 = *(uint32_t*)(Kth + nrow * RS + kb);
            uint32_t bh1 = *(uint32_t*)(Kth + nrow * RS + kb + 16);
            uint32_t bl0 = *(uint32_t*)(Ktl + nrow * RS + kb);
            uint32_t bl1 = *(uint32_t*)(Ktl + nrow * RS + kb + 16);
            mma_bf16(acc[n8], ah, bh0, bh1);
            mma_bf16(acc[n8], ah, bl0, bl1);
            mma_bf16(acc[n8], al, bh0, bh1);
        }
    }

    #pragma unroll
    for (int n8 = 0; n8 < 8; n8++) {
        int h1 = (noff + n8) * 8 + wq * 2;
        *(float2*)&Tp[(size_t)(m0 + rA) * HH + h1]     = make_float2(acc[n8][0], acc[n8][1]);
        *(float2*)&Tp[(size_t)(m0 + rA + 8) * HH + h1] = make_float2(acc[n8][2], acc[n8][3]);
    }
}

// ==================== prefix scan ====================
__global__ void scan_kernel()
{
    int e = blockIdx.x * 256 + threadIdx.x;
    int b = e >> 14;
    int off = e & 16383;
    const size_t base = (((size_t)b * NCHUNK) << 14) + off;

    float a[NCHUNK];
    #pragma unroll
    for (int c = 0; c < NCHUNK; c++)
        a[c] = g_A[base + ((size_t)c << 14)];

    float st = 0.f;
    const float dC = exp2f((float)CC * LG2G);
    #pragma unroll
    for (int c = 0; c < NCHUNK; c++) {
        __nv_bfloat16 h, l;
        split1(st, h, l);
        size_t idx = base + ((size_t)c << 14);
        g_Sth[idx] = h;
        g_Stl[idx] = l;
        st = st * dC + a[c];
    }
}

// ==================== intra + cross output ====================
__global__ __launch_bounds__(512, 1)
void intra_kernel(float* __restrict__ out)
{
    extern __shared__ char sm[];
    char* Qh  = sm;
    char* Ql  = sm + TB;
    char* Xh  = sm + 2*TB;
    char* Xl  = sm + 3*TB;
    char* Sch = sm + 4*TB;
    char* Scl = sm + 5*TB;
    float* gpos = (float*)(sm + 6*TB);
    float* gneg = gpos + 128;

    const int bc = blockIdx.x;
    const int b = bc >> 5;
    const int c = bc & 31;
    const float* Qp = g_Q + (size_t)(b * SS + c * CC) * HH;
    const float* Kp = g_K + (size_t)(b * SS + c * CC) * HH;
    const float* Vp = g_V + (size_t)(b * SS + c * CC) * HH;

    const int tid = threadIdx.x;
    const int wid = tid >> 5;
    const int lane = tid & 31;
    const int rA = lane >> 2;
    const int wq = lane & 3;
    const int i0 = (wid >> 1) * 16;
    const int noff = (wid & 1) * 8;

    if (tid < 128) {
        gpos[tid] = exp2f((float)tid * LG2G);
        gneg[tid] = exp2f(-(float)tid * LG2G);
    }
    __syncthreads();

    load_split_rows_t<512>(Qp, Qh, Ql, tid, nullptr);
    load_split_rows_t<512>(Kp, Xh, Xl, tid, nullptr);
    __syncthreads();

    const int iLo = i0 + rA;
    const int iHi = iLo + 8;

    // ---- Phase 1: S = Q K^T ----
    float acc[8][4];
    #pragma unroll
    for (int n8 = 0; n8 < 8; n8++)
        #pragma unroll
        for (int cc = 0; cc < 4; cc++) acc[n8][cc] = 0.f;

    #pragma unroll
    for (int kk = 0; kk < 8; kk++) {
        const uint32_t kb = kk * 32 + wq * 4;
        uint32_t ah[4], al[4];
        ah[0] = *(uint32_t*)(Qh + iLo * RS + kb);
        ah[1] = *(uint32_t*)(Qh + iHi * RS + kb);
        ah[2] = *(uint32_t*)(Qh + iLo * RS + kb + 16);
        ah[3] = *(uint32_t*)(Qh + iHi * RS + kb + 16);
        al[0] = *(uint32_t*)(Ql + iLo * RS + kb);
        al[1] = *(uint32_t*)(Ql + iHi * RS + kb);
        al[2] = *(uint32_t*)(Ql + iLo * RS + kb + 16);
        al[3] = *(uint32_t*)(Ql + iHi * RS + kb + 16);
        #pragma unroll
        for (int n8 = 0; n8 < 8; n8++) {
            int nrow = (noff + n8) * 8 + rA;
            uint32_t bh0 = *(uint32_t*)(Xh + nrow * RS + kb);
            uint32_t bh1 = *(uint32_t*)(Xh + nrow * RS + kb + 16);
            uint32_t bl0 = *(uint32_t*)(Xl + nrow * RS + kb);
            uint32_t bl1 = *(uint32_t*)(Xl + nrow * RS + kb + 16);
            mma_bf16(acc[n8], ah, bh0, bh1);
            mma_bf16(acc[n8], ah, bl0, bl1);
            mma_bf16(acc[n8], al, bh0, bh1);
        }
    }

    // ---- mask + decay, write S (bf16 hi/lo) to smem ----
    const float gLo = gpos[iLo];
    const float gHi = gpos[iHi];
    #pragma unroll
    for (int n8 = 0; n8 < 8; n8++) {
        int j0 = (noff + n8) * 8 + 2 * wq;
        int j1 = j0 + 1;
        float gn0 = gneg[j0], gn1 = gneg[j1];
        float s0 = (j0 <= iLo) ? acc[n8][0] * (gLo * gn0) : 0.f;
        float s1 = (j1 <= iLo) ? acc[n8][1] * (gLo * gn1) : 0.f;
        float s2 = (j0 <= iHi) ? acc[n8][2] * (gHi * gn0) : 0.f;
        float s3 = (j1 <= iHi) ? acc[n8][3] * (gHi * gn1) : 0.f;
        uint32_t h01 = pack_bf16x2(s0, s1);
        uint32_t h23 = pack_bf16x2(s2, s3);
        float l0 = s0 - __uint_as_float(h01 << 16);
        float l1 = s1 - __uint_as_float(h01 & 0xFFFF0000u);
        float l2 = s2 - __uint_as_float(h23 << 16);
        float l3 = s3 - __uint_as_float(h23 & 0xFFFF0000u);
        uint32_t offLo = (uint32_t)iLo * RS + j0 * 2;
        uint32_t offHi = (uint32_t)iHi * RS + j0 * 2;
        *(uint32_t*)(Sch + offLo) = h01;
        *(uint32_t*)(Sch + offHi) = h23;
        *(uint32_t*)(Scl + offLo) = pack_bf16x2(l0, l1);
        *(uint32_t*)(Scl + offHi) = pack_bf16x2(l2, l3);
    }
    __syncthreads();

    // ---- stage Stt (pre-split) into X ----
    {
        const __nv_bfloat16* Sh = g_Sth + (size_t)bc * HH * HH;
        const __nv_bfloat16* Sl = g_Stl + (size_t)bc * HH * HH;
        #pragma unroll
        for (int it = 0; it < 4; it++) {
            int idx = it * 512 + tid;
            int row = idx >> 4;
            int qv  = idx & 15;
            *(uint4*)(Xh + (uint32_t)row * RS + qv * 16) = *(const uint4*)(Sh + (size_t)row * HH + qv * 8);
            *(uint4*)(Xl + (uint32_t)row * RS + qv * 16) = *(const uint4*)(Sl + (size_t)row * HH + qv * 8);
        }
    }
    __syncthreads();

    // ---- Phase 3b: acc = Q @ St, post-scale rows by gamma^(i+1) ----
    #pragma unroll
    for (int n8 = 0; n8 < 8; n8++)
        #pragma unroll
        for (int cc = 0; cc < 4; cc++) acc[n8][cc] = 0.f;

    #pragma unroll
    for (int kk = 0; kk < 8; kk++) {
        const uint32_t kb = kk * 32 + wq * 4;
        uint32_t ah[4], al[4];
        ah[0] = *(uint32_t*)(Qh + iLo * RS + kb);
        ah[1] = *(uint32_t*)(Qh + iHi * RS + kb);
        ah[2] = *(uint32_t*)(Qh + iLo * RS + kb + 16);
        ah[3] = *(uint32_t*)(Qh + iHi * RS + kb + 16);
        al[0] = *(uint32_t*)(Ql + iLo * RS + kb);
        al[1] = *(uint32_t*)(Ql + iHi * RS + kb);
        al[2] = *(uint32_t*)(Ql + iLo * RS + kb + 16);
        al[3] = *(uint32_t*)(Ql + iHi * RS + kb + 16);
        #pragma unroll
        for (int n8 = 0; n8 < 8; n8++) {
            int nrow = (noff + n8) * 8 + rA;
            uint32_t bh0 = *(uint32_t*)(Xh + nrow * RS + kb);
            uint32_t bh1 = *(uint32_t*)(Xh + nrow * RS + kb + 16);
            uint32_t bl0 = *(uint32_t*)(Xl + nrow * RS + kb);
            uint32_t bl1 = *(uint32_t*)(Xl + nrow * RS + kb + 16);
            mma_bf16(acc[n8], ah, bh0, bh1);
            mma_bf16(acc[n8], ah, bl0, bl1);
            mma_bf16(acc[n8], al, bh0, bh1);
        }
    }

    {
        const float qsLo = gpos[iLo] * GAMMA;
        const float qsHi = gpos[iHi] * GAMMA;
        #pragma unroll
        for (int n8 = 0; n8 < 8; n8++) {
            acc[n8][0] *= qsLo; acc[n8][1] *= qsLo;
            acc[n8][2] *= qsHi; acc[n8][3] *= qsHi;
        }
    }
    __syncthreads();

    load_split_trans_t<512>(Vp, Xh, Xl, tid, nullptr);
    __syncthreads();

    // ---- Phase 3a: acc += S @ V ----
    #pragma unroll
    for (int kk = 0; kk < 8; kk++) {
        const uint32_t kb = kk * 32 + wq * 4;
        uint32_t ah[4], al[4];
        ah[0] = *(uint32_t*)(Sch + iLo * RS + kb);
        ah[1] = *(uint32_t*)(Sch + iHi * RS + kb);
        ah[2] = *(uint32_t*)(Sch + iLo * RS + kb + 16);
        ah[3] = *(uint32_t*)(Sch + iHi * RS + kb + 16);
        al[0] = *(uint32_t*)(Scl + iLo * RS + kb);
        al[1] = *(uint32_t*)(Scl + iHi * RS + kb);
        al[2] = *(uint32_t*)(Scl + iLo * RS + kb + 16);
        al[3] = *(uint32_t*)(Scl + iHi * RS + kb + 16);
        #pragma unroll
        for (int n8 = 0; n8 < 8; n8++) {
            int nrow = (noff + n8) * 8 + rA;
            uint32_t bh0 = *(uint32_t*)(Xh + nrow * RS + kb);
            uint32_t bh1 = *(uint32_t*)(Xh + nrow * RS + kb + 16);
            uint32_t bl0 = *(uint32_t*)(Xl + nrow * RS + kb);
            uint32_t bl1 = *(uint32_t*)(Xl + nrow * RS + kb + 16);
            mma_bf16(acc[n8], ah, bh0, bh1);
            mma_bf16(acc[n8], ah, bl0, bl1);
            mma_bf16(acc[n8], al, bh0, bh1);
        }
    }

    // ---- store O ----
    float* obase = out + (size_t)(b * SS + c * CC) * HH;
    #pragma unroll
    for (int n8 = 0; n8 < 8; n8++) {
        int h2 = (noff + n8) * 8 + wq * 2;
        *(float2*)&obase[(size_t)iLo * HH + h2] = make_float2(acc[n8][0], acc[n8][1]);
        *(float2*)&obase[(size_t)iHi * HH + h2] = make_float2(acc[n8][2], acc[n8][3]);
    }
}

// ====================================================================
extern "C" void kernel_launch(void* const* d_in, const int* in_sizes, int n_in,
                              void* d_out, int out_size)
{
    const float* q  = (const float*)d_in[0];
    const float* k  = (const float*)d_in[1];
    const float* v  = (const float*)d_in[2];
    const float* Wq = (const float*)d_in[3];
    const float* bq = (const float*)d_in[4];
    const float* Wk = (const float*)d_in[5];
    const float* bk = (const float*)d_in[6];
    const float* Wv = (const float*)d_in[7];
    const float* bv = (const float*)d_in[8];
    float* out = (float*)d_out;

    cudaFuncSetAttribute(proj_mma_kernel, cudaFuncAttributeMaxDynamicSharedMemorySize, PROJ_SMEM_ALLOC);
    cudaFuncSetAttribute(chunk_t_kernel, cudaFuncAttributeMaxDynamicSharedMemorySize, CHUNK_SMEM);
    cudaFuncSetAttribute(intra_kernel, cudaFuncAttributeMaxDynamicSharedMemorySize, INTRA_SMEM);

    build_tab_kernel<<<32, 256>>>();

    dim3 gproj(128, 3, 1);
    proj_mma_kernel<<<gproj, 256, PROJ_SMEM_ALLOC>>>(q, k, v, Wq, bq, Wk, bk, Wv, bv);

    chunk_t_kernel<<<BB * NCHUNK, 512, CHUNK_SMEM>>>();
    scan_kernel<<<(BB * HH * HH) / 256, 256>>>();
    intra_kernel<<<BB * NCHUNK, 512, INTRA_SMEM>>>(out);
}

// round 15
// speedup vs baseline: 1.1689x; 1.1689x over previous
#include <cuda_runtime.h>
#include <cuda_bf16.h>
#include <math.h>
#include <stdint.h>

// Problem constants
#define BB 4
#define SS 4096
#define EE 1024
#define HH 128
#define CC 128
#define NCHUNK (SS/CC)
#define GAMMA 0.96875f
#define LG2G  (-0.04580368938794f)
#define LOG2_10000 13.287712379549449

// -------- scratch --------
__device__ float g_Q[BB*SS*HH];
__device__ float g_K[BB*SS*HH];
__device__ float g_V[BB*SS*HH];
__device__ float g_A[BB*NCHUNK*HH*HH];
__device__ __nv_bfloat16 g_Sth[BB*NCHUNK*HH*HH];
__device__ __nv_bfloat16 g_Stl[BB*NCHUNK*HH*HH];
__device__ float4 g_tabA[64][64];
__device__ float4 g_tabB[64][64];

// ==================== table build ====================
__global__ void build_tab_kernel() {
    int idx = blockIdx.x * 256 + threadIdx.x;
    int which = idx >> 12;
    int d  = (idx >> 6) & 63;
    int sX = idx & 63;
    double invf = exp2(-(double)d * (LOG2_10000 / 64.0));
    float sv = (2.0f * (float)d + 51.2f) * (1.0f / 179.2f);
    float ang, pw;
    if (which == 0) { ang = (float)((double)(sX * 64) * invf); pw = powf(sv, (float)sX * 0.125f); }
    else            { ang = (float)((double)sX * invf);        pw = powf(sv, (float)sX * (1.0f/512.0f)); }
    float sn, cs; sincosf(ang, &sn, &cs);
    float4 r = make_float4(sn, cs, pw, 1.0f / pw);
    if (which == 0) g_tabA[d][sX] = r; else g_tabB[d][sX] = r;
}

// ==================== helpers ====================
__device__ __forceinline__ void mma_bf16(float* d, const uint32_t* a, uint32_t b0, uint32_t b1) {
    asm volatile("mma.sync.aligned.m16n8k16.row.col.f32.bf16.bf16.f32 "
        "{%0,%1,%2,%3}, {%4,%5,%6,%7}, {%8,%9}, {%0,%1,%2,%3};"
        : "+f"(d[0]), "+f"(d[1]), "+f"(d[2]), "+f"(d[3])
        : "r"(a[0]), "r"(a[1]), "r"(a[2]), "r"(a[3]), "r"(b0), "r"(b1));
}

__device__ __forceinline__ void mma_f16(float* d, const uint32_t* a, uint32_t b0, uint32_t b1) {
    asm volatile("mma.sync.aligned.m16n8k16.row.col.f32.f16.f16.f32 "
        "{%0,%1,%2,%3}, {%4,%5,%6,%7}, {%8,%9}, {%0,%1,%2,%3};"
        : "+f"(d[0]), "+f"(d[1]), "+f"(d[2]), "+f"(d[3])
        : "r"(a[0]), "r"(a[1]), "r"(a[2]), "r"(a[3]), "r"(b0), "r"(b1));
}

__device__ __forceinline__ uint32_t pack_bf16x2(float x, float y) {
    uint32_t r;
    asm("cvt.rn.bf16x2.f32 %0, %1, %2;" : "=r"(r) : "f"(y), "f"(x));
    return r;
}

__device__ __forceinline__ uint32_t pack_f16x2(float x, float y) {
    uint32_t r;
    asm("cvt.rn.f16x2.f32 %0, %1, %2;" : "=r"(r) : "f"(y), "f"(x));
    return r;
}

__device__ __forceinline__ void split4(float4 v, uint2& hi, uint2& lo) {
    uint32_t hi01 = pack_bf16x2(v.x, v.y);
    uint32_t hi23 = pack_bf16x2(v.z, v.w);
    float l0 = v.x - __uint_as_float(hi01 << 16);
    float l1 = v.y - __uint_as_float(hi01 & 0xFFFF0000u);
    float l2 = v.z - __uint_as_float(hi23 << 16);
    float l3 = v.w - __uint_as_float(hi23 & 0xFFFF0000u);
    hi = make_uint2(hi01, hi23);
    lo = make_uint2(pack_bf16x2(l0, l1), pack_bf16x2(l2, l3));
}

__device__ __forceinline__ void split_store(char* hiP, char* loP, uint32_t off, float4 v) {
    uint2 hi, lo;
    split4(v, hi, lo);
    *(uint2*)(hiP + off) = hi;
    *(uint2*)(loP + off) = lo;
}

__device__ __forceinline__ void split1(float x, __nv_bfloat16& h, __nv_bfloat16& l) {
    h = __float2bfloat16(x);
    l = __float2bfloat16(x - __bfloat162float(h));
}

// ==================== projection GEMM: single-product fp16, 2 CTAs/SM (R13 winner) ====================
#define ROWB 72
#define TILEB (128*ROWB)
#define PROJ_SMEM (4*TILEB)

__device__ __forceinline__ uint32_t lds32(const char* base, int row, int word) {
    return *(const uint32_t*)(base + row * ROWB + word * 4);
}

__global__ __launch_bounds__(256, 2)
void proj_mma_kernel(const float* __restrict__ q, const float* __restrict__ k,
                     const float* __restrict__ v,
                     const float* __restrict__ Wq, const float* __restrict__ bq,
                     const float* __restrict__ Wk, const float* __restrict__ bk,
                     const float* __restrict__ Wv, const float* __restrict__ bv)
{
    extern __shared__ char sm[];
    __shared__ float s_bias[HH];

    const int z = blockIdx.y;
    const float* X   = (z == 0) ? q  : (z == 1) ? k  : v;
    const float* W   = (z == 0) ? Wq : (z == 1) ? Wk : Wv;
    const float* bia = (z == 0) ? bq : (z == 1) ? bk : bv;
    float* OUT       = (z == 0) ? g_Q : (z == 1) ? g_K : g_V;

    const int tid  = threadIdx.x;
    const int wid  = tid >> 5;
    const int lane = tid & 31;
    const int warpM = wid & 3;
    const int warpN = wid >> 2;
    const int m0 = blockIdx.x * 128;

    if (tid < HH) s_bias[tid] = bia[tid];

    #define TILE_PTR(s, wch) (sm + ((s) * 2 + (wch)) * TILEB)

    float acc[2][8][4];
    #pragma unroll
    for (int r = 0; r < 2; r++)
        #pragma unroll
        for (int j = 0; j < 8; j++)
            #pragma unroll
            for (int c = 0; c < 4; c++) acc[r][j][c] = 0.f;

    const int ldRow = tid >> 3;
    const int ldC4  = tid & 7;
    float4 aV[4], wV[4];

    #pragma unroll
    for (int it = 0; it < 4; it++) {
        int row = ldRow + it * 32;
        aV[it] = *(const float4*)&X[(size_t)(m0 + row) * EE + ldC4 * 4];
        wV[it] = *(const float4*)&W[(size_t)row * EE + ldC4 * 4];
    }
    {
        uint32_t off = (uint32_t)ldRow * ROWB + ldC4 * 8;
        #pragma unroll
        for (int it = 0; it < 4; it++) {
            uint32_t o = off + it * 32 * ROWB;
            *(uint2*)(TILE_PTR(0,0) + o) = make_uint2(pack_f16x2(aV[it].x, aV[it].y),
                                                      pack_f16x2(aV[it].z, aV[it].w));
            *(uint2*)(TILE_PTR(0,1) + o) = make_uint2(pack_f16x2(wV[it].x, wV[it].y),
                                                      pack_f16x2(wV[it].z, wV[it].w));
        }
    }
    __syncthreads();

    const int rA = lane >> 2;
    const int wBase = lane & 3;

    for (int i = 0; i < 32; i++) {
        const int s = i & 1;
        if (i < 31) {
            const int k0 = (i + 1) * 32;
            #pragma unroll
            for (int it = 0; it < 4; it++) {
                int row = ldRow + it * 32;
                aV[it] = *(const float4*)&X[(size_t)(m0 + row) * EE + k0 + ldC4 * 4];
                wV[it] = *(const float4*)&W[(size_t)row * EE + k0 + ldC4 * 4];
            }
        }

        const char* At = TILE_PTR(s, 0);
        const char* Wt = TILE_PTR(s, 1);

        #pragma unroll
        for (int k16 = 0; k16 < 2; k16++) {
            const int w = k16 * 8 + wBase;
            uint32_t af[2][4];
            #pragma unroll
            for (int r = 0; r < 2; r++) {
                int row = warpM * 32 + r * 16 + rA;
                af[r][0] = lds32(At, row,     w);
                af[r][1] = lds32(At, row + 8, w);
                af[r][2] = lds32(At, row,     w + 4);
                af[r][3] = lds32(At, row + 8, w + 4);
            }
            #pragma unroll
            for (int j = 0; j < 8; j++) {
                int n = warpN * 64 + j * 8 + rA;
                uint32_t b0 = lds32(Wt, n, w);
                uint32_t b1 = lds32(Wt, n, w + 4);
                #pragma unroll
                for (int r = 0; r < 2; r++)
                    mma_f16(acc[r][j], af[r], b0, b1);
            }
        }

        if (i < 31) {
            uint32_t off = (uint32_t)ldRow * ROWB + ldC4 * 8;
            const int ns = (i + 1) & 1;
            #pragma unroll
            for (int it = 0; it < 4; it++) {
                uint32_t o = off + it * 32 * ROWB;
                *(uint2*)(TILE_PTR(ns,0) + o) = make_uint2(pack_f16x2(aV[it].x, aV[it].y),
                                                           pack_f16x2(aV[it].z, aV[it].w));
                *(uint2*)(TILE_PTR(ns,1) + o) = make_uint2(pack_f16x2(wV[it].x, wV[it].y),
                                                           pack_f16x2(wV[it].z, wV[it].w));
            }
            __syncthreads();
        }
    }

    #pragma unroll
    for (int r = 0; r < 2; r++) {
        #pragma unroll
        for (int half = 0; half < 2; half++) {
            const int m = m0 + warpM * 32 + r * 16 + rA + half * 8;
            const int sIdx = m & (SS - 1);
            const int s1 = sIdx >> 6;
            const int s0 = sIdx & 63;
            float* orow = OUT + (size_t)m * HH;
            #pragma unroll
            for (int j = 0; j < 8; j++) {
                const int h = warpN * 64 + j * 8 + wBase * 2;
                float x0 = acc[r][j][half * 2 + 0] + s_bias[h];
                float x1 = acc[r][j][half * 2 + 1] + s_bias[h + 1];
                if (z == 2) {
                    *(float2*)&orow[h] = make_float2(x0, x1);
                } else {
                    const int d = h >> 1;
                    float4 A4 = g_tabA[d][s1];
                    float4 B4 = g_tabB[d][s0];
                    float sn = A4.x * B4.y + A4.y * B4.x;
                    float cs = A4.y * B4.y - A4.x * B4.x;
                    float sc = (z == 0) ? A4.z * B4.z : A4.w * B4.w;
                    sn *= sc; cs *= sc;
                    *(float2*)&orow[h] = make_float2(x0 * cs - x1 * sn, x1 * cs + x0 * sn);
                }
            }
        }
    }
    #undef TILE_PTR
}

// ==================== shared tile constants for retention kernels ====================
#define RS 272
#define TB (128*RS)
#define CHUNK_SMEM (4*TB + 512)
#define INTRA_SMEM (6*TB + 1024)

template<int NT>
__device__ __forceinline__ void load_split_rows_t(const float* src, char* bh, char* bl,
                                                  int tid, const float* rowScale) {
    #pragma unroll
    for (int it = 0; it < 4096 / NT; it++) {
        int idx = it * NT + tid;
        int row = idx >> 5;
        int c4  = idx & 31;
        float4 v = *(const float4*)&src[(size_t)row * HH + c4 * 4];
        if (rowScale) {
            float s = rowScale[row];
            v.x *= s; v.y *= s; v.z *= s; v.w *= s;
        }
        split_store(bh, bl, (uint32_t)row * RS + c4 * 8, v);
    }
}

// transpose load+split, bank-conflict-reduced pair stores (bf16 hi/lo; R12 winner)
template<int NT>
__device__ __forceinline__ void load_split_trans_t(const float* src, char* bh, char* bl,
                                                   int tid, const float* jScale) {
    #pragma unroll
    for (int it = 0; it < 2048 / NT; it++) {
        int idx = it * NT + tid;
        int h8    = idx & 7;
        int jp2   = (idx >> 3) & 3;
        int houter = (idx >> 5) & 3;
        int jouter = idx >> 7;
        int h4 = houter * 8 + h8;
        int jp = jouter * 4 + jp2;
        int j0 = jp * 2;

        float4 va = *(const float4*)&src[(size_t)j0 * HH + h4 * 4];
        float4 vb = *(const float4*)&src[(size_t)(j0 + 1) * HH + h4 * 4];
        if (jScale) {
            float sa = jScale[j0], sb = jScale[j0 + 1];
            va.x *= sa; va.y *= sa; va.z *= sa; va.w *= sa;
            vb.x *= sb; vb.y *= sb; vb.z *= sb; vb.w *= sb;
        }
        float a[4] = {va.x, va.y, va.z, va.w};
        float b[4] = {vb.x, vb.y, vb.z, vb.w};
        #pragma unroll
        for (int e = 0; e < 4; e++) {
            uint32_t hi = pack_bf16x2(a[e], b[e]);
            float la = a[e] - __uint_as_float(hi << 16);
            float lb = b[e] - __uint_as_float(hi & 0xFFFF0000u);
            uint32_t lo = pack_bf16x2(la, lb);
            uint32_t off = (uint32_t)(h4 * 4 + e) * RS + j0 * 2;
            *(uint32_t*)(bh + off) = hi;
            *(uint32_t*)(bl + off) = lo;
        }
    }
}

// transpose load, fp16 single buffer (for V in intra Phase 3a)
template<int NT>
__device__ __forceinline__ void load_trans_f16_t(const float* src, char* bf, int tid) {
    #pragma unroll
    for (int it = 0; it < 2048 / NT; it++) {
        int idx = it * NT + tid;
        int h8    = idx & 7;
        int jp2   = (idx >> 3) & 3;
        int houter = (idx >> 5) & 3;
        int jouter = idx >> 7;
        int h4 = houter * 8 + h8;
        int jp = jouter * 4 + jp2;
        int j0 = jp * 2;

        float4 va = *(const float4*)&src[(size_t)j0 * HH + h4 * 4];
        float4 vb = *(const float4*)&src[(size_t)(j0 + 1) * HH + h4 * 4];
        float a[4] = {va.x, va.y, va.z, va.w};
        float b[4] = {vb.x, vb.y, vb.z, vb.w};
        #pragma unroll
        for (int e = 0; e < 4; e++) {
            uint32_t off = (uint32_t)(h4 * 4 + e) * RS + j0 * 2;
            *(uint32_t*)(bf + off) = pack_f16x2(a[e], b[e]);
        }
    }
}

// ==================== chunk summary (unchanged from R12/R13) ====================
__global__ __launch_bounds__(512, 1)
void chunk_t_kernel()
{
    extern __shared__ char sm[];
    char* Vth = sm;
    char* Vtl = sm + TB;
    char* Kth = sm + 2*TB;
    char* Ktl = sm + 3*TB;
    float* gpos = (float*)(sm + 4*TB);

    const int bc = blockIdx.x;
    const int b = bc >> 5;
    const int c = bc & 31;
    const float* Kp = g_K + (size_t)(b * SS + c * CC) * HH;
    const float* Vp = g_V + (size_t)(b * SS + c * CC) * HH;
    float* Tp = g_A + (size_t)bc * HH * HH;

    const int tid = threadIdx.x;
    const int wid = tid >> 5;
    const int lane = tid & 31;
    const int rA = lane >> 2;
    const int wq = lane & 3;

    __shared__ float kScale[128];
    if (tid < 128) {
        gpos[tid] = exp2f((float)tid * LG2G);
        kScale[tid] = exp2f((float)(127 - tid) * LG2G);
    }
    __syncthreads();

    load_split_trans_t<512>(Vp, Vth, Vtl, tid, nullptr);
    load_split_trans_t<512>(Kp, Kth, Ktl, tid, kScale);
    __syncthreads();

    const int m0 = (wid >> 1) * 16;
    const int noff = (wid & 1) * 8;
    float acc[8][4];
    #pragma unroll
    for (int n8 = 0; n8 < 8; n8++)
        #pragma unroll
        for (int cc = 0; cc < 4; cc++) acc[n8][cc] = 0.f;

    #pragma unroll
    for (int kk = 0; kk < 8; kk++) {
        const uint32_t kb = kk * 32 + wq * 4;
        uint32_t ah[4], al[4];
        ah[0] = *(uint32_t*)(Vth + (m0 + rA) * RS + kb);
        ah[1] = *(uint32_t*)(Vth + (m0 + rA + 8) * RS + kb);
        ah[2] = *(uint32_t*)(Vth + (m0 + rA) * RS + kb + 16);
        ah[3] = *(uint32_t*)(Vth + (m0 + rA + 8) * RS + kb + 16);
        al[0] = *(uint32_t*)(Vtl + (m0 + rA) * RS + kb);
        al[1] = *(uint32_t*)(Vtl + (m0 + rA + 8) * RS + kb);
        al[2] = *(uint32_t*)(Vtl + (m0 + rA) * RS + kb + 16);
        al[3] = *(uint32_t*)(Vtl + (m0 + rA + 8) * RS + kb + 16);
        #pragma unroll
        for (int n8 = 0; n8 < 8; n8++) {
            int nrow = (noff + n8) * 8 + rA;
            uint32_t bh0 = *(uint32_t*)(Kth + nrow * RS + kb);
            uint32_t bh1 = *(uint32_t*)(Kth + nrow * RS + kb + 16);
            uint32_t bl0 = *(uint32_t*)(Ktl + nrow * RS + kb);
            uint32_t bl1 = *(uint32_t*)(Ktl + nrow * RS + kb + 16);
            mma_bf16(acc[n8], ah, bh0, bh1);
            mma_bf16(acc[n8], ah, bl0, bl1);
            mma_bf16(acc[n8], al, bh0, bh1);
        }
    }

    #pragma unroll
    for (int n8 = 0; n8 < 8; n8++) {
        int h1 = (noff + n8) * 8 + wq * 2;
        *(float2*)&Tp[(size_t)(m0 + rA) * HH + h1]     = make_float2(acc[n8][0], acc[n8][1]);
        *(float2*)&Tp[(size_t)(m0 + rA + 8) * HH + h1] = make_float2(acc[n8][2], acc[n8][3]);
    }
}

// ==================== prefix scan (unchanged) ====================
__global__ void scan_kernel()
{
    int e = blockIdx.x * 256 + threadIdx.x;
    int b = e >> 14;
    int off = e & 16383;
    const size_t base = (((size_t)b * NCHUNK) << 14) + off;

    float a[NCHUNK];
    #pragma unroll
    for (int c = 0; c < NCHUNK; c++)
        a[c] = g_A[base + ((size_t)c << 14)];

    float st = 0.f;
    const float dC = exp2f((float)CC * LG2G);
    #pragma unroll
    for (int c = 0; c < NCHUNK; c++) {
        __nv_bfloat16 h, l;
        split1(st, h, l);
        size_t idx = base + ((size_t)c << 14);
        g_Sth[idx] = h;
        g_Stl[idx] = l;
        st = st * dC + a[c];
    }
}

// ==================== intra + cross output (Phase 3a now fp16 single-product) ====================
__global__ __launch_bounds__(512, 1)
void intra_kernel(float* __restrict__ out)
{
    extern __shared__ char sm[];
    char* Qh  = sm;
    char* Ql  = sm + TB;
    char* Xh  = sm + 2*TB;
    char* Xl  = sm + 3*TB;
    char* Scf = sm + 4*TB;      // masked/decayed scores, fp16, row-major [i][j]
    float* gpos = (float*)(sm + 6*TB);
    float* gneg = gpos + 128;

    const int bc = blockIdx.x;
    const int b = bc >> 5;
    const int c = bc & 31;
    const float* Qp = g_Q + (size_t)(b * SS + c * CC) * HH;
    const float* Kp = g_K + (size_t)(b * SS + c * CC) * HH;
    const float* Vp = g_V + (size_t)(b * SS + c * CC) * HH;

    const int tid = threadIdx.x;
    const int wid = tid >> 5;
    const int lane = tid & 31;
    const int rA = lane >> 2;
    const int wq = lane & 3;
    const int i0 = (wid >> 1) * 16;
    const int noff = (wid & 1) * 8;

    if (tid < 128) {
        gpos[tid] = exp2f((float)tid * LG2G);
        gneg[tid] = exp2f(-(float)tid * LG2G);
    }
    __syncthreads();

    load_split_rows_t<512>(Qp, Qh, Ql, tid, nullptr);
    load_split_rows_t<512>(Kp, Xh, Xl, tid, nullptr);
    __syncthreads();

    const int iLo = i0 + rA;
    const int iHi = iLo + 8;

    // ---- Phase 1: S = Q K^T (bf16x3, exact-ish) ----
    float acc[8][4];
    #pragma unroll
    for (int n8 = 0; n8 < 8; n8++)
        #pragma unroll
        for (int cc = 0; cc < 4; cc++) acc[n8][cc] = 0.f;

    #pragma unroll
    for (int kk = 0; kk < 8; kk++) {
        const uint32_t kb = kk * 32 + wq * 4;
        uint32_t ah[4], al[4];
        ah[0] = *(uint32_t*)(Qh + iLo * RS + kb);
        ah[1] = *(uint32_t*)(Qh + iHi * RS + kb);
        ah[2] = *(uint32_t*)(Qh + iLo * RS + kb + 16);
        ah[3] = *(uint32_t*)(Qh + iHi * RS + kb + 16);
        al[0] = *(uint32_t*)(Ql + iLo * RS + kb);
        al[1] = *(uint32_t*)(Ql + iHi * RS + kb);
        al[2] = *(uint32_t*)(Ql + iLo * RS + kb + 16);
        al[3] = *(uint32_t*)(Ql + iHi * RS + kb + 16);
        #pragma unroll
        for (int n8 = 0; n8 < 8; n8++) {
            int nrow = (noff + n8) * 8 + rA;
            uint32_t bh0 = *(uint32_t*)(Xh + nrow * RS + kb);
            uint32_t bh1 = *(uint32_t*)(Xh + nrow * RS + kb + 16);
            uint32_t bl0 = *(uint32_t*)(Xl + nrow * RS + kb);
            uint32_t bl1 = *(uint32_t*)(Xl + nrow * RS + kb + 16);
            mma_bf16(acc[n8], ah, bh0, bh1);
            mma_bf16(acc[n8], ah, bl0, bl1);
            mma_bf16(acc[n8], al, bh0, bh1);
        }
    }

    // ---- mask + decay, write S (fp16) to smem ----
    const float gLo = gpos[iLo];
    const float gHi = gpos[iHi];
    #pragma unroll
    for (int n8 = 0; n8 < 8; n8++) {
        int j0 = (noff + n8) * 8 + 2 * wq;
        int j1 = j0 + 1;
        float gn0 = gneg[j0], gn1 = gneg[j1];
        float s0 = (j0 <= iLo) ? acc[n8][0] * (gLo * gn0) : 0.f;
        float s1 = (j1 <= iLo) ? acc[n8][1] * (gLo * gn1) : 0.f;
        float s2 = (j0 <= iHi) ? acc[n8][2] * (gHi * gn0) : 0.f;
        float s3 = (j1 <= iHi) ? acc[n8][3] * (gHi * gn1) : 0.f;
        *(uint32_t*)(Scf + (uint32_t)iLo * RS + j0 * 2) = pack_f16x2(s0, s1);
        *(uint32_t*)(Scf + (uint32_t)iHi * RS + j0 * 2) = pack_f16x2(s2, s3);
    }
    __syncthreads();

    // ---- stage Stt (pre-split bf16) into X ----
    {
        const __nv_bfloat16* Sh = g_Sth + (size_t)bc * HH * HH;
        const __nv_bfloat16* Sl = g_Stl + (size_t)bc * HH * HH;
        #pragma unroll
        for (int it = 0; it < 4; it++) {
            int idx = it * 512 + tid;
            int row = idx >> 4;
            int qv  = idx & 15;
            *(uint4*)(Xh + (uint32_t)row * RS + qv * 16) = *(const uint4*)(Sh + (size_t)row * HH + qv * 8);
            *(uint4*)(Xl + (uint32_t)row * RS + qv * 16) = *(const uint4*)(Sl + (size_t)row * HH + qv * 8);
        }
    }
    __syncthreads();

    // ---- Phase 3b: acc = Q @ St (bf16x3), post-scale rows by gamma^(i+1) ----
    #pragma unroll
    for (int n8 = 0; n8 < 8; n8++)
        #pragma unroll
        for (int cc = 0; cc < 4; cc++) acc[n8][cc] = 0.f;

    #pragma unroll
    for (int kk = 0; kk < 8; kk++) {
        const uint32_t kb = kk * 32 + wq * 4;
        uint32_t ah[4], al[4];
        ah[0] = *(uint32_t*)(Qh + iLo * RS + kb);
        ah[1] = *(uint32_t*)(Qh + iHi * RS + kb);
        ah[2] = *(uint32_t*)(Qh + iLo * RS + kb + 16);
        ah[3] = *(uint32_t*)(Qh + iHi * RS + kb + 16);
        al[0] = *(uint32_t*)(Ql + iLo * RS + kb);
        al[1] = *(uint32_t*)(Ql + iHi * RS + kb);
        al[2] = *(uint32_t*)(Ql + iLo * RS + kb + 16);
        al[3] = *(uint32_t*)(Ql + iHi * RS + kb + 16);
        #pragma unroll
        for (int n8 = 0; n8 < 8; n8++) {
            int nrow = (noff + n8) * 8 + rA;
            uint32_t bh0 = *(uint32_t*)(Xh + nrow * RS + kb);
            uint32_t bh1 = *(uint32_t*)(Xh + nrow * RS + kb + 16);
            uint32_t bl0 = *(uint32_t*)(Xl + nrow * RS + kb);
            uint32_t bl1 = *(uint32_t*)(Xl + nrow * RS + kb + 16);
            mma_bf16(acc[n8], ah, bh0, bh1);
            mma_bf16(acc[n8], ah, bl0, bl1);
            mma_bf16(acc[n8], al, bh0, bh1);
        }
    }

    {
        const float qsLo = gpos[iLo] * GAMMA;
        const float qsHi = gpos[iHi] * GAMMA;
        #pragma unroll
        for (int n8 = 0; n8 < 8; n8++) {
            acc[n8][0] *= qsLo; acc[n8][1] *= qsLo;
            acc[n8][2] *= qsHi; acc[n8][3] *= qsHi;
        }
    }
    __syncthreads();

    // ---- stage Vt (fp16 single) into Xh ----
    load_trans_f16_t<512>(Vp, Xh, tid);
    __syncthreads();

    // ---- Phase 3a: acc += S @ V (fp16 single-product) ----
    #pragma unroll
    for (int kk = 0; kk < 8; kk++) {
        const uint32_t kb = kk * 32 + wq * 4;
        uint32_t af[4];
        af[0] = *(uint32_t*)(Scf + iLo * RS + kb);
        af[1] = *(uint32_t*)(Scf + iHi * RS + kb);
        af[2] = *(uint32_t*)(Scf + iLo * RS + kb + 16);
        af[3] = *(uint32_t*)(Scf + iHi * RS + kb + 16);
        #pragma unroll
        for (int n8 = 0; n8 < 8; n8++) {
            int nrow = (noff + n8) * 8 + rA;
            uint32_t b0 = *(uint32_t*)(Xh + nrow * RS + kb);
            uint32_t b1 = *(uint32_t*)(Xh + nrow * RS + kb + 16);
            mma_f16(acc[n8], af, b0, b1);
        }
    }

    // ---- store O ----
    float* obase = out + (size_t)(b * SS + c * CC) * HH;
    #pragma unroll
    for (int n8 = 0; n8 < 8; n8++) {
        int h2 = (noff + n8) * 8 + wq * 2;
        *(float2*)&obase[(size_t)iLo * HH + h2] = make_float2(acc[n8][0], acc[n8][1]);
        *(float2*)&obase[(size_t)iHi * HH + h2] = make_float2(acc[n8][2], acc[n8][3]);
    }
}

// ====================================================================
extern "C" void kernel_launch(void* const* d_in, const int* in_sizes, int n_in,
                              void* d_out, int out_size)
{
    const float* q  = (const float*)d_in[0];
    const float* k  = (const float*)d_in[1];
    const float* v  = (const float*)d_in[2];
    const float* Wq = (const float*)d_in[3];
    const float* bq = (const float*)d_in[4];
    const float* Wk = (const float*)d_in[5];
    const float* bk = (const float*)d_in[6];
    const float* Wv = (const float*)d_in[7];
    const float* bv = (const float*)d_in[8];
    float* out = (float*)d_out;

    cudaFuncSetAttribute(proj_mma_kernel, cudaFuncAttributeMaxDynamicSharedMemorySize, PROJ_SMEM);
    cudaFuncSetAttribute(chunk_t_kernel, cudaFuncAttributeMaxDynamicSharedMemorySize, CHUNK_SMEM);
    cudaFuncSetAttribute(intra_kernel, cudaFuncAttributeMaxDynamicSharedMemorySize, INTRA_SMEM);

    build_tab_kernel<<<32, 256>>>();

    dim3 gproj(128, 3, 1);
    proj_mma_kernel<<<gproj, 256, PROJ_SMEM>>>(q, k, v, Wq, bq, Wk, bk, Wv, bv);

    chunk_t_kernel<<<BB * NCHUNK, 512, CHUNK_SMEM>>>();
    scan_kernel<<<(BB * HH * HH) / 256, 256>>>();
    intra_kernel<<<BB * NCHUNK, 512, INTRA_SMEM>>>(out);
}

// round 16
// speedup vs baseline: 1.2025x; 1.0287x over previous
#include <cuda_runtime.h>
#include <cuda_bf16.h>
#include <math.h>
#include <stdint.h>

// Problem constants
#define BB 4
#define SS 4096
#define EE 1024
#define HH 128
#define CC 128
#define NCHUNK (SS/CC)
#define GAMMA 0.96875f
#define LG2G  (-0.04580368938794f)
#define LOG2_10000 13.287712379549449

// -------- scratch --------
__device__ float g_Q[BB*SS*HH];
__device__ float g_K[BB*SS*HH];
__device__ float g_V[BB*SS*HH];
__device__ float g_A[BB*NCHUNK*HH*HH];          // T'_c (normalized), [h2][h1], fp32
__device__ __nv_bfloat16 g_Sth[BB*NCHUNK*HH*HH];
__device__ __nv_bfloat16 g_Stl[BB*NCHUNK*HH*HH];
__device__ float4 g_tabA[64][64];
__device__ float4 g_tabB[64][64];

// ==================== table build ====================
__global__ void build_tab_kernel() {
    int idx = blockIdx.x * 256 + threadIdx.x;
    int which = idx >> 12;
    int d  = (idx >> 6) & 63;
    int sX = idx & 63;
    double invf = exp2(-(double)d * (LOG2_10000 / 64.0));
    float sv = (2.0f * (float)d + 51.2f) * (1.0f / 179.2f);
    float ang, pw;
    if (which == 0) { ang = (float)((double)(sX * 64) * invf); pw = powf(sv, (float)sX * 0.125f); }
    else            { ang = (float)((double)sX * invf);        pw = powf(sv, (float)sX * (1.0f/512.0f)); }
    float sn, cs; sincosf(ang, &sn, &cs);
    float4 r = make_float4(sn, cs, pw, 1.0f / pw);
    if (which == 0) g_tabA[d][sX] = r; else g_tabB[d][sX] = r;
}

// ==================== helpers ====================
__device__ __forceinline__ void mma_bf16(float* d, const uint32_t* a, uint32_t b0, uint32_t b1) {
    asm volatile("mma.sync.aligned.m16n8k16.row.col.f32.bf16.bf16.f32 "
        "{%0,%1,%2,%3}, {%4,%5,%6,%7}, {%8,%9}, {%0,%1,%2,%3};"
        : "+f"(d[0]), "+f"(d[1]), "+f"(d[2]), "+f"(d[3])
        : "r"(a[0]), "r"(a[1]), "r"(a[2]), "r"(a[3]), "r"(b0), "r"(b1));
}

__device__ __forceinline__ void mma_f16(float* d, const uint32_t* a, uint32_t b0, uint32_t b1) {
    asm volatile("mma.sync.aligned.m16n8k16.row.col.f32.f16.f16.f32 "
        "{%0,%1,%2,%3}, {%4,%5,%6,%7}, {%8,%9}, {%0,%1,%2,%3};"
        : "+f"(d[0]), "+f"(d[1]), "+f"(d[2]), "+f"(d[3])
        : "r"(a[0]), "r"(a[1]), "r"(a[2]), "r"(a[3]), "r"(b0), "r"(b1));
}

__device__ __forceinline__ uint32_t pack_bf16x2(float x, float y) {
    uint32_t r;
    asm("cvt.rn.bf16x2.f32 %0, %1, %2;" : "=r"(r) : "f"(y), "f"(x));
    return r;
}

__device__ __forceinline__ uint32_t pack_f16x2(float x, float y) {
    uint32_t r;
    asm("cvt.rn.f16x2.f32 %0, %1, %2;" : "=r"(r) : "f"(y), "f"(x));
    return r;
}

__device__ __forceinline__ void split4(float4 v, uint2& hi, uint2& lo) {
    uint32_t hi01 = pack_bf16x2(v.x, v.y);
    uint32_t hi23 = pack_bf16x2(v.z, v.w);
    float l0 = v.x - __uint_as_float(hi01 << 16);
    float l1 = v.y - __uint_as_float(hi01 & 0xFFFF0000u);
    float l2 = v.z - __uint_as_float(hi23 << 16);
    float l3 = v.w - __uint_as_float(hi23 & 0xFFFF0000u);
    hi = make_uint2(hi01, hi23);
    lo = make_uint2(pack_bf16x2(l0, l1), pack_bf16x2(l2, l3));
}

__device__ __forceinline__ void split_store(char* hiP, char* loP, uint32_t off, float4 v) {
    uint2 hi, lo;
    split4(v, hi, lo);
    *(uint2*)(hiP + off) = hi;
    *(uint2*)(loP + off) = lo;
}

__device__ __forceinline__ void split1(float x, __nv_bfloat16& h, __nv_bfloat16& l) {
    h = __float2bfloat16(x);
    l = __float2bfloat16(x - __bfloat162float(h));
}

// ==================== projection GEMM (exact R13/R15 winner) ====================
#define ROWB 72
#define TILEB (128*ROWB)
#define PROJ_SMEM (4*TILEB)

__device__ __forceinline__ uint32_t lds32(const char* base, int row, int word) {
    return *(const uint32_t*)(base + row * ROWB + word * 4);
}

__global__ __launch_bounds__(256, 2)
void proj_mma_kernel(const float* __restrict__ q, const float* __restrict__ k,
                     const float* __restrict__ v,
                     const float* __restrict__ Wq, const float* __restrict__ bq,
                     const float* __restrict__ Wk, const float* __restrict__ bk,
                     const float* __restrict__ Wv, const float* __restrict__ bv)
{
    extern __shared__ char sm[];
    __shared__ float s_bias[HH];

    const int z = blockIdx.y;
    const float* X   = (z == 0) ? q  : (z == 1) ? k  : v;
    const float* W   = (z == 0) ? Wq : (z == 1) ? Wk : Wv;
    const float* bia = (z == 0) ? bq : (z == 1) ? bk : bv;
    float* OUT       = (z == 0) ? g_Q : (z == 1) ? g_K : g_V;

    const int tid  = threadIdx.x;
    const int wid  = tid >> 5;
    const int lane = tid & 31;
    const int warpM = wid & 3;
    const int warpN = wid >> 2;
    const int m0 = blockIdx.x * 128;

    if (tid < HH) s_bias[tid] = bia[tid];

    #define TILE_PTR(s, wch) (sm + ((s) * 2 + (wch)) * TILEB)

    float acc[2][8][4];
    #pragma unroll
    for (int r = 0; r < 2; r++)
        #pragma unroll
        for (int j = 0; j < 8; j++)
            #pragma unroll
            for (int c = 0; c < 4; c++) acc[r][j][c] = 0.f;

    const int ldRow = tid >> 3;
    const int ldC4  = tid & 7;
    float4 aV[4], wV[4];

    #pragma unroll
    for (int it = 0; it < 4; it++) {
        int row = ldRow + it * 32;
        aV[it] = *(const float4*)&X[(size_t)(m0 + row) * EE + ldC4 * 4];
        wV[it] = *(const float4*)&W[(size_t)row * EE + ldC4 * 4];
    }
    {
        uint32_t off = (uint32_t)ldRow * ROWB + ldC4 * 8;
        #pragma unroll
        for (int it = 0; it < 4; it++) {
            uint32_t o = off + it * 32 * ROWB;
            *(uint2*)(TILE_PTR(0,0) + o) = make_uint2(pack_f16x2(aV[it].x, aV[it].y),
                                                      pack_f16x2(aV[it].z, aV[it].w));
            *(uint2*)(TILE_PTR(0,1) + o) = make_uint2(pack_f16x2(wV[it].x, wV[it].y),
                                                      pack_f16x2(wV[it].z, wV[it].w));
        }
    }
    __syncthreads();

    const int rA = lane >> 2;
    const int wBase = lane & 3;

    for (int i = 0; i < 32; i++) {
        const int s = i & 1;
        if (i < 31) {
            const int k0 = (i + 1) * 32;
            #pragma unroll
            for (int it = 0; it < 4; it++) {
                int row = ldRow + it * 32;
                aV[it] = *(const float4*)&X[(size_t)(m0 + row) * EE + k0 + ldC4 * 4];
                wV[it] = *(const float4*)&W[(size_t)row * EE + k0 + ldC4 * 4];
            }
        }

        const char* At = TILE_PTR(s, 0);
        const char* Wt = TILE_PTR(s, 1);

        #pragma unroll
        for (int k16 = 0; k16 < 2; k16++) {
            const int w = k16 * 8 + wBase;
            uint32_t af[2][4];
            #pragma unroll
            for (int r = 0; r < 2; r++) {
                int row = warpM * 32 + r * 16 + rA;
                af[r][0] = lds32(At, row,     w);
                af[r][1] = lds32(At, row + 8, w);
                af[r][2] = lds32(At, row,     w + 4);
                af[r][3] = lds32(At, row + 8, w + 4);
            }
            #pragma unroll
            for (int j = 0; j < 8; j++) {
                int n = warpN * 64 + j * 8 + rA;
                uint32_t b0 = lds32(Wt, n, w);
                uint32_t b1 = lds32(Wt, n, w + 4);
                #pragma unroll
                for (int r = 0; r < 2; r++)
                    mma_f16(acc[r][j], af[r], b0, b1);
            }
        }

        if (i < 31) {
            uint32_t off = (uint32_t)ldRow * ROWB + ldC4 * 8;
            const int ns = (i + 1) & 1;
            #pragma unroll
            for (int it = 0; it < 4; it++) {
                uint32_t o = off + it * 32 * ROWB;
                *(uint2*)(TILE_PTR(ns,0) + o) = make_uint2(pack_f16x2(aV[it].x, aV[it].y),
                                                           pack_f16x2(aV[it].z, aV[it].w));
                *(uint2*)(TILE_PTR(ns,1) + o) = make_uint2(pack_f16x2(wV[it].x, wV[it].y),
                                                           pack_f16x2(wV[it].z, wV[it].w));
            }
            __syncthreads();
        }
    }

    #pragma unroll
    for (int r = 0; r < 2; r++) {
        #pragma unroll
        for (int half = 0; half < 2; half++) {
            const int m = m0 + warpM * 32 + r * 16 + rA + half * 8;
            const int sIdx = m & (SS - 1);
            const int s1 = sIdx >> 6;
            const int s0 = sIdx & 63;
            float* orow = OUT + (size_t)m * HH;
            #pragma unroll
            for (int j = 0; j < 8; j++) {
                const int h = warpN * 64 + j * 8 + wBase * 2;
                float x0 = acc[r][j][half * 2 + 0] + s_bias[h];
                float x1 = acc[r][j][half * 2 + 1] + s_bias[h + 1];
                if (z == 2) {
                    *(float2*)&orow[h] = make_float2(x0, x1);
                } else {
                    const int d = h >> 1;
                    float4 A4 = g_tabA[d][s1];
                    float4 B4 = g_tabB[d][s0];
                    float sn = A4.x * B4.y + A4.y * B4.x;
                    float cs = A4.y * B4.y - A4.x * B4.x;
                    float sc = (z == 0) ? A4.z * B4.z : A4.w * B4.w;
                    sn *= sc; cs *= sc;
                    *(float2*)&orow[h] = make_float2(x0 * cs - x1 * sn, x1 * cs + x0 * sn);
                }
            }
        }
    }
    #undef TILE_PTR
}

// ==================== shared tile constants for retention kernels ====================
#define RS 272
#define TB (128*RS)
#define CHUNK_SMEM (2*TB + 1024)
#define INTRA_SMEM (5*TB + 2048)

template<int NT>
__device__ __forceinline__ void load_split_rows_t(const float* src, char* bh, char* bl,
                                                  int tid, const float* rowScale) {
    #pragma unroll
    for (int it = 0; it < 4096 / NT; it++) {
        int idx = it * NT + tid;
        int row = idx >> 5;
        int c4  = idx & 31;
        float4 v = *(const float4*)&src[(size_t)row * HH + c4 * 4];
        if (rowScale) {
            float s = rowScale[row];
            v.x *= s; v.y *= s; v.z *= s; v.w *= s;
        }
        split_store(bh, bl, (uint32_t)row * RS + c4 * 8, v);
    }
}

// row-major fp16 load with per-column scale (or reciprocal of it)
template<int NT, bool INV>
__device__ __forceinline__ void load_rows_f16_sc(const float* src, char* bf,
                                                 int tid, const float* colScale) {
    #pragma unroll
    for (int it = 0; it < 4096 / NT; it++) {
        int idx = it * NT + tid;
        int row = idx >> 5;
        int c4  = idx & 31;
        float4 v = *(const float4*)&src[(size_t)row * HH + c4 * 4];
        float s0 = colScale[c4*4+0], s1 = colScale[c4*4+1];
        float s2 = colScale[c4*4+2], s3 = colScale[c4*4+3];
        if (INV) { s0 = 1.0f/s0; s1 = 1.0f/s1; s2 = 1.0f/s2; s3 = 1.0f/s3; }
        *(uint2*)(bf + (uint32_t)row * RS + c4 * 8) =
            make_uint2(pack_f16x2(v.x*s0, v.y*s1), pack_f16x2(v.z*s2, v.w*s3));
    }
}

// transpose load, fp16 (bank-conflict-reduced pair stores); optional row(j)/col(h) scales
template<int NT>
__device__ __forceinline__ void load_trans_f16_t(const float* src, char* bf, int tid,
                                                 const float* jScale, const float* hScale) {
    #pragma unroll
    for (int it = 0; it < 2048 / NT; it++) {
        int idx = it * NT + tid;
        int h8    = idx & 7;
        int jp2   = (idx >> 3) & 3;
        int houter = (idx >> 5) & 3;
        int jouter = idx >> 7;
        int h4 = houter * 8 + h8;
        int jp = jouter * 4 + jp2;
        int j0 = jp * 2;

        float4 va = *(const float4*)&src[(size_t)j0 * HH + h4 * 4];
        float4 vb = *(const float4*)&src[(size_t)(j0 + 1) * HH + h4 * 4];
        if (jScale) {
            float sa = jScale[j0], sb = jScale[j0 + 1];
            va.x *= sa; va.y *= sa; va.z *= sa; va.w *= sa;
            vb.x *= sb; vb.y *= sb; vb.z *= sb; vb.w *= sb;
        }
        float a[4] = {va.x, va.y, va.z, va.w};
        float b[4] = {vb.x, vb.y, vb.z, vb.w};
        #pragma unroll
        for (int e = 0; e < 4; e++) {
            float cs = hScale ? hScale[h4 * 4 + e] : 1.0f;
            uint32_t off = (uint32_t)(h4 * 4 + e) * RS + j0 * 2;
            *(uint32_t*)(bf + off) = pack_f16x2(a[e] * cs, b[e] * cs);
        }
    }
}

// ==================== chunk summary: fp16 single-product with per-chunk renorm ====================
// T'_c[h2][h1] = sum_j V[j,h2] * (gamma^(127-j) * fsc_{d(h1)} * K[j,h1]),  fsc_d = sv_d^((128c+64)/512)
__global__ __launch_bounds__(512, 1)
void chunk_t_kernel()
{
    extern __shared__ char sm[];
    char* Vtf = sm;
    char* Ktf = sm + TB;
    float* kJ   = (float*)(sm + 2*TB);     // gamma^(127-j)
    float* fscK = kJ + 128;                // sv_d^p

    const int bc = blockIdx.x;
    const int b = bc >> 5;
    const int c = bc & 31;
    const float* Kp = g_K + (size_t)(b * SS + c * CC) * HH;
    const float* Vp = g_V + (size_t)(b * SS + c * CC) * HH;
    float* Tp = g_A + (size_t)bc * HH * HH;

    const int tid = threadIdx.x;
    const int wid = tid >> 5;
    const int lane = tid & 31;
    const int rA = lane >> 2;
    const int wq = lane & 3;

    const float p = (float)(c * 128 + 64) * (1.0f / 512.0f);
    if (tid < 128) {
        kJ[tid] = exp2f((float)(127 - tid) * LG2G);
        float sv = (2.0f * (float)(tid >> 1) + 51.2f) * (1.0f / 179.2f);
        fscK[tid] = exp2f(log2f(sv) * p);
    }
    __syncthreads();

    load_trans_f16_t<512>(Vp, Vtf, tid, nullptr, nullptr);
    load_trans_f16_t<512>(Kp, Ktf, tid, kJ, fscK);
    __syncthreads();

    const int m0 = (wid >> 1) * 16;
    const int noff = (wid & 1) * 8;
    float acc[8][4];
    #pragma unroll
    for (int n8 = 0; n8 < 8; n8++)
        #pragma unroll
        for (int cc = 0; cc < 4; cc++) acc[n8][cc] = 0.f;

    #pragma unroll
    for (int kk = 0; kk < 8; kk++) {
        const uint32_t kb = kk * 32 + wq * 4;
        uint32_t af[4];
        af[0] = *(uint32_t*)(Vtf + (m0 + rA) * RS + kb);
        af[1] = *(uint32_t*)(Vtf + (m0 + rA + 8) * RS + kb);
        af[2] = *(uint32_t*)(Vtf + (m0 + rA) * RS + kb + 16);
        af[3] = *(uint32_t*)(Vtf + (m0 + rA + 8) * RS + kb + 16);
        #pragma unroll
        for (int n8 = 0; n8 < 8; n8++) {
            int nrow = (noff + n8) * 8 + rA;
            uint32_t b0 = *(uint32_t*)(Ktf + nrow * RS + kb);
            uint32_t b1 = *(uint32_t*)(Ktf + nrow * RS + kb + 16);
            mma_f16(acc[n8], af, b0, b1);
        }
    }

    #pragma unroll
    for (int n8 = 0; n8 < 8; n8++) {
        int h1 = (noff + n8) * 8 + wq * 2;
        *(float2*)&Tp[(size_t)(m0 + rA) * HH + h1]     = make_float2(acc[n8][0], acc[n8][1]);
        *(float2*)&Tp[(size_t)(m0 + rA + 8) * HH + h1] = make_float2(acc[n8][2], acc[n8][3]);
    }
}

// ==================== prefix scan: un-normalize T' then accumulate ====================
__global__ void scan_kernel()
{
    int e = blockIdx.x * 256 + threadIdx.x;
    int b = e >> 14;
    int off = e & 16383;
    const size_t base = (((size_t)b * NCHUNK) << 14) + off;

    const int h1 = off & 127;
    const float sv = (2.0f * (float)(h1 >> 1) + 51.2f) * (1.0f / 179.2f);
    const float l2 = log2f(sv);

    float a[NCHUNK];
    #pragma unroll
    for (int c = 0; c < NCHUNK; c++)
        a[c] = g_A[base + ((size_t)c << 14)];

    float st = 0.f;
    const float dC = exp2f((float)CC * LG2G);
    #pragma unroll
    for (int c = 0; c < NCHUNK; c++) {
        __nv_bfloat16 h, l;
        split1(st, h, l);
        size_t idx = base + ((size_t)c << 14);
        g_Sth[idx] = h;
        g_Stl[idx] = l;
        float u = exp2f(-l2 * ((float)(c * 128 + 64) * (1.0f / 512.0f)));
        st = st * dC + a[c] * u;
    }
}

// ==================== intra + cross output ====================
// Phase 1 fp16 single-product via per-chunk renorm; 3b bf16x3; 3a fp16 single.
__global__ __launch_bounds__(512, 1)
void intra_kernel(float* __restrict__ out)
{
    extern __shared__ char sm[];
    char* T1  = sm;             // Qf (fp16 norm) -> Qh (bf16 hi)
    char* T2  = sm + TB;        // Kf (fp16 norm) -> Ql (bf16 lo)
    char* Xh  = sm + 2*TB;      // Stt hi -> Vt fp16
    char* Xl  = sm + 3*TB;      // Stt lo
    char* Scf = sm + 4*TB;      // masked/decayed scores, fp16
    float* gpos = (float*)(sm + 5*TB);
    float* gneg = gpos + 128;
    float* fsc  = gpos + 256;

    const int bc = blockIdx.x;
    const int b = bc >> 5;
    const int c = bc & 31;
    const float* Qp = g_Q + (size_t)(b * SS + c * CC) * HH;
    const float* Kp = g_K + (size_t)(b * SS + c * CC) * HH;
    const float* Vp = g_V + (size_t)(b * SS + c * CC) * HH;

    const int tid = threadIdx.x;
    const int wid = tid >> 5;
    const int lane = tid & 31;
    const int rA = lane >> 2;
    const int wq = lane & 3;
    const int i0 = (wid >> 1) * 16;
    const int noff = (wid & 1) * 8;

    const float p = (float)(c * 128 + 64) * (1.0f / 512.0f);
    if (tid < 128) {
        gpos[tid] = exp2f((float)tid * LG2G);
        gneg[tid] = exp2f(-(float)tid * LG2G);
        float sv = (2.0f * (float)(tid >> 1) + 51.2f) * (1.0f / 179.2f);
        fsc[tid] = exp2f(log2f(sv) * p);
    }
    __syncthreads();

    // Qf = Q / fsc, Kf = K * fsc  (both fp16, factors cancel termwise in d)
    load_rows_f16_sc<512, true >(Qp, T1, tid, fsc);
    load_rows_f16_sc<512, false>(Kp, T2, tid, fsc);
    __syncthreads();

    const int iLo = i0 + rA;
    const int iHi = iLo + 8;

    // ---- Phase 1: S = Qf Kf^T (fp16 single product) ----
    float acc[8][4];
    #pragma unroll
    for (int n8 = 0; n8 < 8; n8++)
        #pragma unroll
        for (int cc = 0; cc < 4; cc++) acc[n8][cc] = 0.f;

    #pragma unroll
    for (int kk = 0; kk < 8; kk++) {
        const uint32_t kb = kk * 32 + wq * 4;
        uint32_t af[4];
        af[0] = *(uint32_t*)(T1 + iLo * RS + kb);
        af[1] = *(uint32_t*)(T1 + iHi * RS + kb);
        af[2] = *(uint32_t*)(T1 + iLo * RS + kb + 16);
        af[3] = *(uint32_t*)(T1 + iHi * RS + kb + 16);
        #pragma unroll
        for (int n8 = 0; n8 < 8; n8++) {
            int nrow = (noff + n8) * 8 + rA;
            uint32_t b0 = *(uint32_t*)(T2 + nrow * RS + kb);
            uint32_t b1 = *(uint32_t*)(T2 + nrow * RS + kb + 16);
            mma_f16(acc[n8], af, b0, b1);
        }
    }

    // ---- mask + decay, write S (fp16) to smem ----
    const float gLo = gpos[iLo];
    const float gHi = gpos[iHi];
    #pragma unroll
    for (int n8 = 0; n8 < 8; n8++) {
        int j0 = (noff + n8) * 8 + 2 * wq;
        int j1 = j0 + 1;
        float gn0 = gneg[j0], gn1 = gneg[j1];
        float s0 = (j0 <= iLo) ? acc[n8][0] * (gLo * gn0) : 0.f;
        float s1 = (j1 <= iLo) ? acc[n8][1] * (gLo * gn1) : 0.f;
        float s2 = (j0 <= iHi) ? acc[n8][2] * (gHi * gn0) : 0.f;
        float s3 = (j1 <= iHi) ? acc[n8][3] * (gHi * gn1) : 0.f;
        *(uint32_t*)(Scf + (uint32_t)iLo * RS + j0 * 2) = pack_f16x2(s0, s1);
        *(uint32_t*)(Scf + (uint32_t)iHi * RS + j0 * 2) = pack_f16x2(s2, s3);
    }
    __syncthreads();   // phase-1 reads done; T1/T2 can be overwritten

    // ---- reload Q as bf16 hi/lo; stage Stt ----
    load_split_rows_t<512>(Qp, T1, T2, tid, nullptr);
    {
        const __nv_bfloat16* Sh = g_Sth + (size_t)bc * HH * HH;
        const __nv_bfloat16* Sl = g_Stl + (size_t)bc * HH * HH;
        #pragma unroll
        for (int it = 0; it < 4; it++) {
            int idx = it * 512 + tid;
            int row = idx >> 4;
            int qv  = idx & 15;
            *(uint4*)(Xh + (uint32_t)row * RS + qv * 16) = *(const uint4*)(Sh + (size_t)row * HH + qv * 8);
            *(uint4*)(Xl + (uint32_t)row * RS + qv * 16) = *(const uint4*)(Sl + (size_t)row * HH + qv * 8);
        }
    }
    __syncthreads();

    // ---- Phase 3b: acc = Q @ St (bf16x3), post-scale rows by gamma^(i+1) ----
    #pragma unroll
    for (int n8 = 0; n8 < 8; n8++)
        #pragma unroll
        for (int cc = 0; cc < 4; cc++) acc[n8][cc] = 0.f;

    #pragma unroll
    for (int kk = 0; kk < 8; kk++) {
        const uint32_t kb = kk * 32 + wq * 4;
        uint32_t ah[4], al[4];
        ah[0] = *(uint32_t*)(T1 + iLo * RS + kb);
        ah[1] = *(uint32_t*)(T1 + iHi * RS + kb);
        ah[2] = *(uint32_t*)(T1 + iLo * RS + kb + 16);
        ah[3] = *(uint32_t*)(T1 + iHi * RS + kb + 16);
        al[0] = *(uint32_t*)(T2 + iLo * RS + kb);
        al[1] = *(uint32_t*)(T2 + iHi * RS + kb);
        al[2] = *(uint32_t*)(T2 + iLo * RS + kb + 16);
        al[3] = *(uint32_t*)(T2 + iHi * RS + kb + 16);
        #pragma unroll
        for (int n8 = 0; n8 < 8; n8++) {
            int nrow = (noff + n8) * 8 + rA;
            uint32_t bh0 = *(uint32_t*)(Xh + nrow * RS + kb);
            uint32_t bh1 = *(uint32_t*)(Xh + nrow * RS + kb + 16);
            uint32_t bl0 = *(uint32_t*)(Xl + nrow * RS + kb);
            uint32_t bl1 = *(uint32_t*)(Xl + nrow * RS + kb + 16);
            mma_bf16(acc[n8], ah, bh0, bh1);
            mma_bf16(acc[n8], ah, bl0, bl1);
            mma_bf16(acc[n8], al, bh0, bh1);
        }
    }

    {
        const float qsLo = gpos[iLo] * GAMMA;
        const float qsHi = gpos[iHi] * GAMMA;
        #pragma unroll
        for (int n8 = 0; n8 < 8; n8++) {
            acc[n8][0] *= qsLo; acc[n8][1] *= qsLo;
            acc[n8][2] *= qsHi; acc[n8][3] *= qsHi;
        }
    }
    __syncthreads();

    // ---- stage Vt (fp16) into Xh ----
    load_trans_f16_t<512>(Vp, Xh, tid, nullptr, nullptr);
    __syncthreads();

    // ---- Phase 3a: acc += S @ V (fp16 single product) ----
    #pragma unroll
    for (int kk = 0; kk < 8; kk++) {
        const uint32_t kb = kk * 32 + wq * 4;
        uint32_t af[4];
        af[0] = *(uint32_t*)(Scf + iLo * RS + kb);
        af[1] = *(uint32_t*)(Scf + iHi * RS + kb);
        af[2] = *(uint32_t*)(Scf + iLo * RS + kb + 16);
        af[3] = *(uint32_t*)(Scf + iHi * RS + kb + 16);
        #pragma unroll
        for (int n8 = 0; n8 < 8; n8++) {
            int nrow = (noff + n8) * 8 + rA;
            uint32_t b0 = *(uint32_t*)(Xh + nrow * RS + kb);
            uint32_t b1 = *(uint32_t*)(Xh + nrow * RS + kb + 16);
            mma_f16(acc[n8], af, b0, b1);
        }
    }

    // ---- store O ----
    float* obase = out + (size_t)(b * SS + c * CC) * HH;
    #pragma unroll
    for (int n8 = 0; n8 < 8; n8++) {
        int h2 = (noff + n8) * 8 + wq * 2;
        *(float2*)&obase[(size_t)iLo * HH + h2] = make_float2(acc[n8][0], acc[n8][1]);
        *(float2*)&obase[(size_t)iHi * HH + h2] = make_float2(acc[n8][2], acc[n8][3]);
    }
}

// ====================================================================
extern "C" void kernel_launch(void* const* d_in, const int* in_sizes, int n_in,
                              void* d_out, int out_size)
{
    const float* q  = (const float*)d_in[0];
    const float* k  = (const float*)d_in[1];
    const float* v  = (const float*)d_in[2];
    const float* Wq = (const float*)d_in[3];
    const float* bq = (const float*)d_in[4];
    const float* Wk = (const float*)d_in[5];
    const float* bk = (const float*)d_in[6];
    const float* Wv = (const float*)d_in[7];
    const float* bv = (const float*)d_in[8];
    float* out = (float*)d_out;

    cudaFuncSetAttribute(proj_mma_kernel, cudaFuncAttributeMaxDynamicSharedMemorySize, PROJ_SMEM);
    cudaFuncSetAttribute(chunk_t_kernel, cudaFuncAttributeMaxDynamicSharedMemorySize, CHUNK_SMEM);
    cudaFuncSetAttribute(intra_kernel, cudaFuncAttributeMaxDynamicSharedMemorySize, INTRA_SMEM);

    build_tab_kernel<<<32, 256>>>();

    dim3 gproj(128, 3, 1);
    proj_mma_kernel<<<gproj, 256, PROJ_SMEM>>>(q, k, v, Wq, bq, Wk, bk, Wv, bv);

    chunk_t_kernel<<<BB * NCHUNK, 512, CHUNK_SMEM>>>();
    scan_kernel<<<(BB * HH * HH) / 256, 256>>>();
    intra_kernel<<<BB * NCHUNK, 512, INTRA_SMEM>>>(out);
}

// round 17
// speedup vs baseline: 1.2030x; 1.0004x over previous
#include <cuda_runtime.h>
#include <cuda_bf16.h>
#include <cuda_fp16.h>
#include <math.h>
#include <stdint.h>

// Problem constants
#define BB 4
#define SS 4096
#define EE 1024
#define HH 128
#define CC 128
#define NCHUNK (SS/CC)
#define GAMMA 0.96875f
#define LG2G  (-0.04580368938794f)
#define LOG2_10000 13.287712379549449

// -------- scratch --------
__device__ float g_Q[BB*SS*HH];
__device__ float g_K[BB*SS*HH];
__device__ float g_V[BB*SS*HH];
__device__ float g_A[BB*NCHUNK*HH*HH];          // T'_c (normalized), [h2][h1], fp32
__device__ __half g_Sth[BB*NCHUNK*HH*HH];       // normalized state St', fp16 hi
__device__ __half g_Stl[BB*NCHUNK*HH*HH];       // normalized state St', fp16 lo
__device__ float4 g_tabA[64][64];
__device__ float4 g_tabB[64][64];

// ==================== table build ====================
__global__ void build_tab_kernel() {
    int idx = blockIdx.x * 256 + threadIdx.x;
    int which = idx >> 12;
    int d  = (idx >> 6) & 63;
    int sX = idx & 63;
    double invf = exp2(-(double)d * (LOG2_10000 / 64.0));
    float sv = (2.0f * (float)d + 51.2f) * (1.0f / 179.2f);
    float ang, pw;
    if (which == 0) { ang = (float)((double)(sX * 64) * invf); pw = powf(sv, (float)sX * 0.125f); }
    else            { ang = (float)((double)sX * invf);        pw = powf(sv, (float)sX * (1.0f/512.0f)); }
    float sn, cs; sincosf(ang, &sn, &cs);
    float4 r = make_float4(sn, cs, pw, 1.0f / pw);
    if (which == 0) g_tabA[d][sX] = r; else g_tabB[d][sX] = r;
}

// ==================== helpers ====================
__device__ __forceinline__ void mma_f16(float* d, const uint32_t* a, uint32_t b0, uint32_t b1) {
    asm volatile("mma.sync.aligned.m16n8k16.row.col.f32.f16.f16.f32 "
        "{%0,%1,%2,%3}, {%4,%5,%6,%7}, {%8,%9}, {%0,%1,%2,%3};"
        : "+f"(d[0]), "+f"(d[1]), "+f"(d[2]), "+f"(d[3])
        : "r"(a[0]), "r"(a[1]), "r"(a[2]), "r"(a[3]), "r"(b0), "r"(b1));
}

__device__ __forceinline__ uint32_t pack_f16x2(float x, float y) {
    uint32_t r;
    asm("cvt.rn.f16x2.f32 %0, %1, %2;" : "=r"(r) : "f"(y), "f"(x));
    return r;
}

// ==================== projection GEMM (exact R13/R15 winner) ====================
#define ROWB 72
#define TILEB (128*ROWB)
#define PROJ_SMEM (4*TILEB)

__device__ __forceinline__ uint32_t lds32(const char* base, int row, int word) {
    return *(const uint32_t*)(base + row * ROWB + word * 4);
}

__global__ __launch_bounds__(256, 2)
void proj_mma_kernel(const float* __restrict__ q, const float* __restrict__ k,
                     const float* __restrict__ v,
                     const float* __restrict__ Wq, const float* __restrict__ bq,
                     const float* __restrict__ Wk, const float* __restrict__ bk,
                     const float* __restrict__ Wv, const float* __restrict__ bv)
{
    extern __shared__ char sm[];
    __shared__ float s_bias[HH];

    const int z = blockIdx.y;
    const float* X   = (z == 0) ? q  : (z == 1) ? k  : v;
    const float* W   = (z == 0) ? Wq : (z == 1) ? Wk : Wv;
    const float* bia = (z == 0) ? bq : (z == 1) ? bk : bv;
    float* OUT       = (z == 0) ? g_Q : (z == 1) ? g_K : g_V;

    const int tid  = threadIdx.x;
    const int wid  = tid >> 5;
    const int lane = tid & 31;
    const int warpM = wid & 3;
    const int warpN = wid >> 2;
    const int m0 = blockIdx.x * 128;

    if (tid < HH) s_bias[tid] = bia[tid];

    #define TILE_PTR(s, wch) (sm + ((s) * 2 + (wch)) * TILEB)

    float acc[2][8][4];
    #pragma unroll
    for (int r = 0; r < 2; r++)
        #pragma unroll
        for (int j = 0; j < 8; j++)
            #pragma unroll
            for (int c = 0; c < 4; c++) acc[r][j][c] = 0.f;

    const int ldRow = tid >> 3;
    const int ldC4  = tid & 7;
    float4 aV[4], wV[4];

    #pragma unroll
    for (int it = 0; it < 4; it++) {
        int row = ldRow + it * 32;
        aV[it] = *(const float4*)&X[(size_t)(m0 + row) * EE + ldC4 * 4];
        wV[it] = *(const float4*)&W[(size_t)row * EE + ldC4 * 4];
    }
    {
        uint32_t off = (uint32_t)ldRow * ROWB + ldC4 * 8;
        #pragma unroll
        for (int it = 0; it < 4; it++) {
            uint32_t o = off + it * 32 * ROWB;
            *(uint2*)(TILE_PTR(0,0) + o) = make_uint2(pack_f16x2(aV[it].x, aV[it].y),
                                                      pack_f16x2(aV[it].z, aV[it].w));
            *(uint2*)(TILE_PTR(0,1) + o) = make_uint2(pack_f16x2(wV[it].x, wV[it].y),
                                                      pack_f16x2(wV[it].z, wV[it].w));
        }
    }
    __syncthreads();

    const int rA = lane >> 2;
    const int wBase = lane & 3;

    for (int i = 0; i < 32; i++) {
        const int s = i & 1;
        if (i < 31) {
            const int k0 = (i + 1) * 32;
            #pragma unroll
            for (int it = 0; it < 4; it++) {
                int row = ldRow + it * 32;
                aV[it] = *(const float4*)&X[(size_t)(m0 + row) * EE + k0 + ldC4 * 4];
                wV[it] = *(const float4*)&W[(size_t)row * EE + k0 + ldC4 * 4];
            }
        }

        const char* At = TILE_PTR(s, 0);
        const char* Wt = TILE_PTR(s, 1);

        #pragma unroll
        for (int k16 = 0; k16 < 2; k16++) {
            const int w = k16 * 8 + wBase;
            uint32_t af[2][4];
            #pragma unroll
            for (int r = 0; r < 2; r++) {
                int row = warpM * 32 + r * 16 + rA;
                af[r][0] = lds32(At, row,     w);
                af[r][1] = lds32(At, row + 8, w);
                af[r][2] = lds32(At, row,     w + 4);
                af[r][3] = lds32(At, row + 8, w + 4);
            }
            #pragma unroll
            for (int j = 0; j < 8; j++) {
                int n = warpN * 64 + j * 8 + rA;
                uint32_t b0 = lds32(Wt, n, w);
                uint32_t b1 = lds32(Wt, n, w + 4);
                #pragma unroll
                for (int r = 0; r < 2; r++)
                    mma_f16(acc[r][j], af[r], b0, b1);
            }
        }

        if (i < 31) {
            uint32_t off = (uint32_t)ldRow * ROWB + ldC4 * 8;
            const int ns = (i + 1) & 1;
            #pragma unroll
            for (int it = 0; it < 4; it++) {
                uint32_t o = off + it * 32 * ROWB;
                *(uint2*)(TILE_PTR(ns,0) + o) = make_uint2(pack_f16x2(aV[it].x, aV[it].y),
                                                           pack_f16x2(aV[it].z, aV[it].w));
                *(uint2*)(TILE_PTR(ns,1) + o) = make_uint2(pack_f16x2(wV[it].x, wV[it].y),
                                                           pack_f16x2(wV[it].z, wV[it].w));
            }
            __syncthreads();
        }
    }

    #pragma unroll
    for (int r = 0; r < 2; r++) {
        #pragma unroll
        for (int half = 0; half < 2; half++) {
            const int m = m0 + warpM * 32 + r * 16 + rA + half * 8;
            const int sIdx = m & (SS - 1);
            const int s1 = sIdx >> 6;
            const int s0 = sIdx & 63;
            float* orow = OUT + (size_t)m * HH;
            #pragma unroll
            for (int j = 0; j < 8; j++) {
                const int h = warpN * 64 + j * 8 + wBase * 2;
                float x0 = acc[r][j][half * 2 + 0] + s_bias[h];
                float x1 = acc[r][j][half * 2 + 1] + s_bias[h + 1];
                if (z == 2) {
                    *(float2*)&orow[h] = make_float2(x0, x1);
                } else {
                    const int d = h >> 1;
                    float4 A4 = g_tabA[d][s1];
                    float4 B4 = g_tabB[d][s0];
                    float sn = A4.x * B4.y + A4.y * B4.x;
                    float cs = A4.y * B4.y - A4.x * B4.x;
                    float sc = (z == 0) ? A4.z * B4.z : A4.w * B4.w;
                    sn *= sc; cs *= sc;
                    *(float2*)&orow[h] = make_float2(x0 * cs - x1 * sn, x1 * cs + x0 * sn);
                }
            }
        }
    }
    #undef TILE_PTR
}

// ==================== shared tile constants for retention kernels ====================
#define RS 272
#define TB (128*RS)
#define CHUNK_SMEM (2*TB + 1024)
#define INTRA_SMEM (5*TB + 2048)

// row-major fp16 load with per-column scale (or reciprocal of it)
template<int NT, bool INV>
__device__ __forceinline__ void load_rows_f16_sc(const float* src, char* bf,
                                                 int tid, const float* colScale) {
    #pragma unroll
    for (int it = 0; it < 4096 / NT; it++) {
        int idx = it * NT + tid;
        int row = idx >> 5;
        int c4  = idx & 31;
        float4 v = *(const float4*)&src[(size_t)row * HH + c4 * 4];
        float s0 = colScale[c4*4+0], s1 = colScale[c4*4+1];
        float s2 = colScale[c4*4+2], s3 = colScale[c4*4+3];
        if (INV) { s0 = 1.0f/s0; s1 = 1.0f/s1; s2 = 1.0f/s2; s3 = 1.0f/s3; }
        *(uint2*)(bf + (uint32_t)row * RS + c4 * 8) =
            make_uint2(pack_f16x2(v.x*s0, v.y*s1), pack_f16x2(v.z*s2, v.w*s3));
    }
}

// transpose load, fp16 (bank-conflict-reduced pair stores); optional row(j)/col(h) scales
template<int NT>
__device__ __forceinline__ void load_trans_f16_t(const float* src, char* bf, int tid,
                                                 const float* jScale, const float* hScale) {
    #pragma unroll
    for (int it = 0; it < 2048 / NT; it++) {
        int idx = it * NT + tid;
        int h8    = idx & 7;
        int jp2   = (idx >> 3) & 3;
        int houter = (idx >> 5) & 3;
        int jouter = idx >> 7;
        int h4 = houter * 8 + h8;
        int jp = jouter * 4 + jp2;
        int j0 = jp * 2;

        float4 va = *(const float4*)&src[(size_t)j0 * HH + h4 * 4];
        float4 vb = *(const float4*)&src[(size_t)(j0 + 1) * HH + h4 * 4];
        if (jScale) {
            float sa = jScale[j0], sb = jScale[j0 + 1];
            va.x *= sa; va.y *= sa; va.z *= sa; va.w *= sa;
            vb.x *= sb; vb.y *= sb; vb.z *= sb; vb.w *= sb;
        }
        float a[4] = {va.x, va.y, va.z, va.w};
        float b[4] = {vb.x, vb.y, vb.z, vb.w};
        #pragma unroll
        for (int e = 0; e < 4; e++) {
            float cs = hScale ? hScale[h4 * 4 + e] : 1.0f;
            uint32_t off = (uint32_t)(h4 * 4 + e) * RS + j0 * 2;
            *(uint32_t*)(bf + off) = pack_f16x2(a[e] * cs, b[e] * cs);
        }
    }
}

// ==================== chunk summary (unchanged from R16) ====================
__global__ __launch_bounds__(512, 1)
void chunk_t_kernel()
{
    extern __shared__ char sm[];
    char* Vtf = sm;
    char* Ktf = sm + TB;
    float* kJ   = (float*)(sm + 2*TB);
    float* fscK = kJ + 128;

    const int bc = blockIdx.x;
    const int b = bc >> 5;
    const int c = bc & 31;
    const float* Kp = g_K + (size_t)(b * SS + c * CC) * HH;
    const float* Vp = g_V + (size_t)(b * SS + c * CC) * HH;
    float* Tp = g_A + (size_t)bc * HH * HH;

    const int tid = threadIdx.x;
    const int wid = tid >> 5;
    const int lane = tid & 31;
    const int rA = lane >> 2;
    const int wq = lane & 3;

    const float p = (float)(c * 128 + 64) * (1.0f / 512.0f);
    if (tid < 128) {
        kJ[tid] = exp2f((float)(127 - tid) * LG2G);
        float sv = (2.0f * (float)(tid >> 1) + 51.2f) * (1.0f / 179.2f);
        fscK[tid] = exp2f(log2f(sv) * p);
    }
    __syncthreads();

    load_trans_f16_t<512>(Vp, Vtf, tid, nullptr, nullptr);
    load_trans_f16_t<512>(Kp, Ktf, tid, kJ, fscK);
    __syncthreads();

    const int m0 = (wid >> 1) * 16;
    const int noff = (wid & 1) * 8;
    float acc[8][4];
    #pragma unroll
    for (int n8 = 0; n8 < 8; n8++)
        #pragma unroll
        for (int cc = 0; cc < 4; cc++) acc[n8][cc] = 0.f;

    #pragma unroll
    for (int kk = 0; kk < 8; kk++) {
        const uint32_t kb = kk * 32 + wq * 4;
        uint32_t af[4];
        af[0] = *(uint32_t*)(Vtf + (m0 + rA) * RS + kb);
        af[1] = *(uint32_t*)(Vtf + (m0 + rA + 8) * RS + kb);
        af[2] = *(uint32_t*)(Vtf + (m0 + rA) * RS + kb + 16);
        af[3] = *(uint32_t*)(Vtf + (m0 + rA + 8) * RS + kb + 16);
        #pragma unroll
        for (int n8 = 0; n8 < 8; n8++) {
            int nrow = (noff + n8) * 8 + rA;
            uint32_t b0 = *(uint32_t*)(Ktf + nrow * RS + kb);
            uint32_t b1 = *(uint32_t*)(Ktf + nrow * RS + kb + 16);
            mma_f16(acc[n8], af, b0, b1);
        }
    }

    #pragma unroll
    for (int n8 = 0; n8 < 8; n8++) {
        int h1 = (noff + n8) * 8 + wq * 2;
        *(float2*)&Tp[(size_t)(m0 + rA) * HH + h1]     = make_float2(acc[n8][0], acc[n8][1]);
        *(float2*)&Tp[(size_t)(m0 + rA + 8) * HH + h1] = make_float2(acc[n8][2], acc[n8][3]);
    }
}

// ==================== prefix scan: states stored NORMALIZED (St' = St * fsc_c), fp16 hi/lo ====================
__global__ void scan_kernel()
{
    int e = blockIdx.x * 256 + threadIdx.x;
    int b = e >> 14;
    int off = e & 16383;
    const size_t base = (((size_t)b * NCHUNK) << 14) + off;

    const int h1 = off & 127;
    const float sv = (2.0f * (float)(h1 >> 1) + 51.2f) * (1.0f / 179.2f);
    const float l2 = log2f(sv);

    float a[NCHUNK];
    #pragma unroll
    for (int c = 0; c < NCHUNK; c++)
        a[c] = g_A[base + ((size_t)c << 14)];

    float st = 0.f;   // raw frame
    const float dC = exp2f((float)CC * LG2G);
    #pragma unroll
    for (int c = 0; c < NCHUNK; c++) {
        const float pc = (float)(c * 128 + 64) * (1.0f / 512.0f);
        const float un = exp2f(l2 * pc);       // fsc_c = sv^pc
        float stn = st * un;                   // normalized state St'
        __half h = __float2half(stn);
        __half l = __float2half(stn - __half2float(h));
        size_t idx = base + ((size_t)c << 14);
        g_Sth[idx] = h;
        g_Stl[idx] = l;
        st = st * dC + a[c] * exp2f(-l2 * pc); // un-normalize T'
    }
}

// ==================== intra + cross output ====================
// P1: Qf Kf^T fp16; P3b: Qf @ St' (fp16 hi+lo, fsc cancels); P3a: S @ V fp16.
__global__ __launch_bounds__(512, 1)
void intra_kernel(float* __restrict__ out)
{
    extern __shared__ char sm[];
    char* T1  = sm;             // Qf (fp16, normalized) — persists through P3b
    char* T2  = sm + TB;        // Kf (fp16)
    char* Xh  = sm + 2*TB;      // St' hi -> Vt fp16
    char* Xl  = sm + 3*TB;      // St' lo
    char* Scf = sm + 4*TB;      // masked/decayed scores, fp16
    float* gpos = (float*)(sm + 5*TB);
    float* gneg = gpos + 128;
    float* fsc  = gpos + 256;

    const int bc = blockIdx.x;
    const int b = bc >> 5;
    const int c = bc & 31;
    const float* Qp = g_Q + (size_t)(b * SS + c * CC) * HH;
    const float* Kp = g_K + (size_t)(b * SS + c * CC) * HH;
    const float* Vp = g_V + (size_t)(b * SS + c * CC) * HH;

    const int tid = threadIdx.x;
    const int wid = tid >> 5;
    const int lane = tid & 31;
    const int rA = lane >> 2;
    const int wq = lane & 3;
    const int i0 = (wid >> 1) * 16;
    const int noff = (wid & 1) * 8;

    const float p = (float)(c * 128 + 64) * (1.0f / 512.0f);
    if (tid < 128) {
        gpos[tid] = exp2f((float)tid * LG2G);
        gneg[tid] = exp2f(-(float)tid * LG2G);
        float sv = (2.0f * (float)(tid >> 1) + 51.2f) * (1.0f / 179.2f);
        fsc[tid] = exp2f(log2f(sv) * p);
    }
    __syncthreads();

    // Qf = Q / fsc, Kf = K * fsc
    load_rows_f16_sc<512, true >(Qp, T1, tid, fsc);
    load_rows_f16_sc<512, false>(Kp, T2, tid, fsc);

    // stage St' (fp16 hi/lo) into Xh/Xl — independent of T1/T2
    {
        const __half* Sh = g_Sth + (size_t)bc * HH * HH;
        const __half* Sl = g_Stl + (size_t)bc * HH * HH;
        #pragma unroll
        for (int it = 0; it < 4; it++) {
            int idx = it * 512 + tid;
            int row = idx >> 4;
            int qv  = idx & 15;
            *(uint4*)(Xh + (uint32_t)row * RS + qv * 16) = *(const uint4*)(Sh + (size_t)row * HH + qv * 8);
            *(uint4*)(Xl + (uint32_t)row * RS + qv * 16) = *(const uint4*)(Sl + (size_t)row * HH + qv * 8);
        }
    }
    __syncthreads();

    const int iLo = i0 + rA;
    const int iHi = iLo + 8;

    // ---- Phase 1: S = Qf Kf^T (fp16 single product) ----
    float acc[8][4];
    #pragma unroll
    for (int n8 = 0; n8 < 8; n8++)
        #pragma unroll
        for (int cc = 0; cc < 4; cc++) acc[n8][cc] = 0.f;

    #pragma unroll
    for (int kk = 0; kk < 8; kk++) {
        const uint32_t kb = kk * 32 + wq * 4;
        uint32_t af[4];
        af[0] = *(uint32_t*)(T1 + iLo * RS + kb);
        af[1] = *(uint32_t*)(T1 + iHi * RS + kb);
        af[2] = *(uint32_t*)(T1 + iLo * RS + kb + 16);
        af[3] = *(uint32_t*)(T1 + iHi * RS + kb + 16);
        #pragma unroll
        for (int n8 = 0; n8 < 8; n8++) {
            int nrow = (noff + n8) * 8 + rA;
            uint32_t b0 = *(uint32_t*)(T2 + nrow * RS + kb);
            uint32_t b1 = *(uint32_t*)(T2 + nrow * RS + kb + 16);
            mma_f16(acc[n8], af, b0, b1);
        }
    }

    // ---- mask + decay, write S (fp16) to smem ----
    const float gLo = gpos[iLo];
    const float gHi = gpos[iHi];
    #pragma unroll
    for (int n8 = 0; n8 < 8; n8++) {
        int j0 = (noff + n8) * 8 + 2 * wq;
        int j1 = j0 + 1;
        float gn0 = gneg[j0], gn1 = gneg[j1];
        float s0 = (j0 <= iLo) ? acc[n8][0] * (gLo * gn0) : 0.f;
        float s1 = (j1 <= iLo) ? acc[n8][1] * (gLo * gn1) : 0.f;
        float s2 = (j0 <= iHi) ? acc[n8][2] * (gHi * gn0) : 0.f;
        float s3 = (j1 <= iHi) ? acc[n8][3] * (gHi * gn1) : 0.f;
        *(uint32_t*)(Scf + (uint32_t)iLo * RS + j0 * 2) = pack_f16x2(s0, s1);
        *(uint32_t*)(Scf + (uint32_t)iHi * RS + j0 * 2) = pack_f16x2(s2, s3);
    }

    // ---- Phase 3b: acc = Qf @ St' (fp16, 2 products; fsc cancels), post-scale by gamma^(i+1) ----
    #pragma unroll
    for (int n8 = 0; n8 < 8; n8++)
        #pragma unroll
        for (int cc = 0; cc < 4; cc++) acc[n8][cc] = 0.f;

    #pragma unroll
    for (int kk = 0; kk < 8; kk++) {
        const uint32_t kb = kk * 32 + wq * 4;
        uint32_t af[4];
        af[0] = *(uint32_t*)(T1 + iLo * RS + kb);
        af[1] = *(uint32_t*)(T1 + iHi * RS + kb);
        af[2] = *(uint32_t*)(T1 + iLo * RS + kb + 16);
        af[3] = *(uint32_t*)(T1 + iHi * RS + kb + 16);
        #pragma unroll
        for (int n8 = 0; n8 < 8; n8++) {
            int nrow = (noff + n8) * 8 + rA;
            uint32_t bh0 = *(uint32_t*)(Xh + nrow * RS + kb);
            uint32_t bh1 = *(uint32_t*)(Xh + nrow * RS + kb + 16);
            uint32_t bl0 = *(uint32_t*)(Xl + nrow * RS + kb);
            uint32_t bl1 = *(uint32_t*)(Xl + nrow * RS + kb + 16);
            mma_f16(acc[n8], af, bh0, bh1);
            mma_f16(acc[n8], af, bl0, bl1);
        }
    }

    {
        const float qsLo = gpos[iLo] * GAMMA;
        const float qsHi = gpos[iHi] * GAMMA;
        #pragma unroll
        for (int n8 = 0; n8 < 8; n8++) {
            acc[n8][0] *= qsLo; acc[n8][1] *= qsLo;
            acc[n8][2] *= qsHi; acc[n8][3] *= qsHi;
        }
    }
    __syncthreads();   // all reads of Xh/Xl and writes of Scf complete

    // ---- stage Vt (fp16) into Xh ----
    load_trans_f16_t<512>(Vp, Xh, tid, nullptr, nullptr);
    __syncthreads();

    // ---- Phase 3a: acc += S @ V (fp16 single product) ----
    #pragma unroll
    for (int kk = 0; kk < 8; kk++) {
        const uint32_t kb = kk * 32 + wq * 4;
        uint32_t af[4];
        af[0] = *(uint32_t*)(Scf + iLo * RS + kb);
        af[1] = *(uint32_t*)(Scf + iHi * RS + kb);
        af[2] = *(uint32_t*)(Scf + iLo * RS + kb + 16);
        af[3] = *(uint32_t*)(Scf + iHi * RS + kb + 16);
        #pragma unroll
        for (int n8 = 0; n8 < 8; n8++) {
            int nrow = (noff + n8) * 8 + rA;
            uint32_t b0 = *(uint32_t*)(Xh + nrow * RS + kb);
            uint32_t b1 = *(uint32_t*)(Xh + nrow * RS + kb + 16);
            mma_f16(acc[n8], af, b0, b1);
        }
    }

    // ---- store O ----
    float* obase = out + (size_t)(b * SS + c * CC) * HH;
    #pragma unroll
    for (int n8 = 0; n8 < 8; n8++) {
        int h2 = (noff + n8) * 8 + wq * 2;
        *(float2*)&obase[(size_t)iLo * HH + h2] = make_float2(acc[n8][0], acc[n8][1]);
        *(float2*)&obase[(size_t)iHi * HH + h2] = make_float2(acc[n8][2], acc[n8][3]);
    }
}

// ====================================================================
extern "C" void kernel_launch(void* const* d_in, const int* in_sizes, int n_in,
                              void* d_out, int out_size)
{
    const float* q  = (const float*)d_in[0];
    const float* k  = (const float*)d_in[1];
    const float* v  = (const float*)d_in[2];
    const float* Wq = (const float*)d_in[3];
    const float* bq = (const float*)d_in[4];
    const float* Wk = (const float*)d_in[5];
    const float* bk = (const float*)d_in[6];
    const float* Wv = (const float*)d_in[7];
    const float* bv = (const float*)d_in[8];
    float* out = (float*)d_out;

    cudaFuncSetAttribute(proj_mma_kernel, cudaFuncAttributeMaxDynamicSharedMemorySize, PROJ_SMEM);
    cudaFuncSetAttribute(chunk_t_kernel, cudaFuncAttributeMaxDynamicSharedMemorySize, CHUNK_SMEM);
    cudaFuncSetAttribute(intra_kernel, cudaFuncAttributeMaxDynamicSharedMemorySize, INTRA_SMEM);

    build_tab_kernel<<<32, 256>>>();

    dim3 gproj(128, 3, 1);
    proj_mma_kernel<<<gproj, 256, PROJ_SMEM>>>(q, k, v, Wq, bq, Wk, bk, Wv, bv);

    chunk_t_kernel<<<BB * NCHUNK, 512, CHUNK_SMEM>>>();
    scan_kernel<<<(BB * HH * HH) / 256, 256>>>();
    intra_kernel<<<BB * NCHUNK, 512, INTRA_SMEM>>>(out);
}